// round 8
// baseline (speedup 1.0000x reference)
#include <cuda_runtime.h>
#include <math.h>
#include <stdint.h>

#define DIM   4096
#define NH    32
#define HD    128
#define BSZ   2
#define SEQ   2048
#define NTOK  (BSZ*SEQ)          // 4096 tokens

// ---------------- scratch (allocation-free: __device__ globals) -------------
__device__ float g_q  [(size_t)NTOK * DIM];   // rotated Q (tf32 bits)
__device__ float g_att[(size_t)NTOK * DIM];   // attention out (tf32 bits)
__device__ float g_xt [(size_t)NTOK * DIM];   // tf32+perm x / reused for abuf-perm
__device__ float g_wqt[(size_t)DIM * DIM];    // tf32+perm weights
__device__ float g_wkt[(size_t)DIM * DIM];
__device__ float g_wvt[(size_t)DIM * DIM];
__device__ float g_wot[(size_t)DIM * DIM];

// ============================================================================
// helpers
// ============================================================================
__device__ __forceinline__ uint32_t smem_u32(const void* p) {
    uint32_t a;
    asm("{ .reg .u64 t; cvta.to.shared.u64 t, %1; cvt.u32.u64 %0, t; }"
        : "=r"(a) : "l"(p));
    return a;
}

__device__ __forceinline__ void cp16(uint32_t dst, const void* src) {
    asm volatile("cp.async.cg.shared.global [%0], [%1], 16;" :: "r"(dst), "l"(src));
}
#define CP_COMMIT() asm volatile("cp.async.commit_group;" ::: "memory")
#define CP_WAIT1()  asm volatile("cp.async.wait_group 1;"  ::: "memory")

__device__ __forceinline__ uint32_t f2tf(float f) {
    uint32_t r;
    asm("cvt.rna.tf32.f32 %0, %1;" : "=r"(r) : "f"(f));
    return r;
}
__device__ __forceinline__ float f2tf_f(float f) { return __uint_as_float(f2tf(f)); }

__device__ __forceinline__ void mma16n8k8(float* c, const uint32_t* a, const uint32_t* b) {
    asm volatile(
        "mma.sync.aligned.m16n8k8.row.col.f32.tf32.tf32.f32 "
        "{%0,%1,%2,%3}, {%4,%5,%6,%7}, {%8,%9}, {%0,%1,%2,%3};"
        : "+f"(c[0]), "+f"(c[1]), "+f"(c[2]), "+f"(c[3])
        : "r"(a[0]), "r"(a[1]), "r"(a[2]), "r"(a[3]), "r"(b[0]), "r"(b[1]));
}

// ============================================================================
// tf32 rounding + k-group permutation pass.
// Each 8-float k-group [a0..a7] stored as [a0,a4,a1,a5,a2,a6,a3,a7] so the
// (kc, kc+4) mma fragment pair is one aligned float2 in smem.
// ============================================================================
__global__ __launch_bounds__(256) void cvt_perm(const float4* __restrict__ in,
                                                float4* __restrict__ out, int n8) {
    int i = blockIdx.x * blockDim.x + threadIdx.x;
    if (i < n8) {
        float4 a = in[2 * i], b = in[2 * i + 1];
        float4 o0 = {f2tf_f(a.x), f2tf_f(b.x), f2tf_f(a.y), f2tf_f(b.y)};
        float4 o1 = {f2tf_f(a.z), f2tf_f(b.z), f2tf_f(a.w), f2tf_f(b.w)};
        out[2 * i]     = o0;
        out[2 * i + 1] = o1;
    }
}

// ============================================================================
// tf32 mma.sync GEMM (NT), cvt-free, float2 fragment loads (permuted K).
// C[m,n] = sum_k A[m,k]*B[n,k];  M=NTOK, N=K=4096
// CTA 256x128, 512 threads: 16 warps (4x4), warp tile 64x32, BK=32,
// 3-stage cp.async pipeline. 4 warps/SMSP for tensor-pipe saturation.
// smem row stride 40 floats: LDS.64 conflict-free per 16-lane phase.
// blockIdx.z selects (B, C, rope) — fused QKV in one launch.
// ============================================================================
#define GTM 256
#define GTN 128
#define GBK 32
#define GTS 40
#define GST 3
#define GNKI (DIM / GBK)                                   // 128
#define G_STAGE ((GTM + GTN) * GTS)                        // floats per stage
#define G_SMEM (GST * G_STAGE * 4)                         // 184320 B

__global__ __launch_bounds__(512, 1) void gemm_mma(
    const float* __restrict__ A,
    const float* __restrict__ B0, const float* __restrict__ B1, const float* __restrict__ B2,
    float* __restrict__ C0, float* __restrict__ C1, float* __restrict__ C2,
    const float* __restrict__ rcs, const float* __restrict__ rsn) {
    extern __shared__ float smf[];

    const int z = blockIdx.z;
    const float* B = (z == 0) ? B0 : ((z == 1) ? B1 : B2);
    float*       C = (z == 0) ? C0 : ((z == 1) ? C1 : C2);
    const bool do_rope = (rcs != nullptr) && (z < 2);

    const int t    = threadIdx.x;
    const int lane = t & 31;
    const int w    = t >> 5;          // 0..15
    const int wm   = w >> 2;          // 0..3  (64-row slab)
    const int wn   = w & 3;           // 0..3  (32-col slab)
    const int g    = lane >> 2;       // 0..7
    const int q    = lane & 3;        // 0..3
    const int bm   = blockIdx.y, bn = blockIdx.x;

    const uint32_t sS = smem_u32(smf);
    const int lr  = t >> 3;           // 0..63
    const int lc4 = (t & 7) * 4;      // 0,4,...,28
    const float* Agp = A + (size_t)(bm * GTM + lr) * DIM + lc4;
    const float* Bgp = B + (size_t)(bn * GTN + lr) * DIM + lc4;

    float acc[4][4][4];
#pragma unroll
    for (int i = 0; i < 4; i++)
#pragma unroll
        for (int j = 0; j < 4; j++)
#pragma unroll
            for (int v = 0; v < 4; v++) acc[i][j][v] = 0.f;

    // prologue: stages 0..GST-2
#pragma unroll
    for (int s = 0; s < GST - 1; s++) {
        const int k0 = s * GBK;
        const uint32_t dA = sS + s * (G_STAGE * 4);
        const uint32_t dB = dA + GTM * GTS * 4;
#pragma unroll
        for (int j = 0; j < 4; j++)
            cp16(dA + ((lr + j * 64) * GTS + lc4) * 4, Agp + (size_t)(j * 64) * DIM + k0);
#pragma unroll
        for (int j = 0; j < 2; j++)
            cp16(dB + ((lr + j * 64) * GTS + lc4) * 4, Bgp + (size_t)(j * 64) * DIM + k0);
        CP_COMMIT();
    }

    for (int i = 0; i < GNKI; i++) {
        CP_WAIT1();
        __syncthreads();

        if (i + GST - 1 < GNKI) {
            const int st = (i + GST - 1) % GST;
            const int k0 = (i + GST - 1) * GBK;
            const uint32_t dA = sS + st * (G_STAGE * 4);
            const uint32_t dB = dA + GTM * GTS * 4;
#pragma unroll
            for (int j = 0; j < 4; j++)
                cp16(dA + ((lr + j * 64) * GTS + lc4) * 4, Agp + (size_t)(j * 64) * DIM + k0);
#pragma unroll
            for (int j = 0; j < 2; j++)
                cp16(dB + ((lr + j * 64) * GTS + lc4) * 4, Bgp + (size_t)(j * 64) * DIM + k0);
        }
        CP_COMMIT();   // empty in tail: keeps group accounting valid

        const float* Ab = smf + (i % GST) * G_STAGE;
        const float* Bb = Ab + GTM * GTS;
#pragma unroll
        for (int k8 = 0; k8 < 4; k8++) {
            const int ks = k8 * 8 + 2 * q;        // permuted slot of (kc, kc+4)
            uint32_t af[4][4], bf[4][2];
#pragma unroll
            for (int mt = 0; mt < 4; mt++) {
                const int r0 = wm * 64 + mt * 16 + g;
                float2 u0 = *(const float2*)(Ab + r0 * GTS + ks);
                float2 u1 = *(const float2*)(Ab + (r0 + 8) * GTS + ks);
                af[mt][0] = __float_as_uint(u0.x);
                af[mt][1] = __float_as_uint(u1.x);
                af[mt][2] = __float_as_uint(u0.y);
                af[mt][3] = __float_as_uint(u1.y);
            }
#pragma unroll
            for (int nt = 0; nt < 4; nt++) {
                const int c0 = wn * 32 + nt * 8 + g;
                float2 v = *(const float2*)(Bb + c0 * GTS + ks);
                bf[nt][0] = __float_as_uint(v.x);
                bf[nt][1] = __float_as_uint(v.y);
            }
#pragma unroll
            for (int mt = 0; mt < 4; mt++)
#pragma unroll
                for (int nt = 0; nt < 4; nt++)
                    mma16n8k8(acc[mt][nt], af[mt], bf[nt]);
        }
    }

    // epilogue (fused RoPE for Q/K: accumulator col pairs ARE rotary pairs)
#pragma unroll
    for (int mt = 0; mt < 4; mt++) {
        const size_t row = (size_t)bm * GTM + wm * 64 + mt * 16 + g;
#pragma unroll
        for (int nt = 0; nt < 4; nt++) {
            const int col = bn * GTN + wn * 32 + nt * 8 + q * 2;
            float2 v0 = {acc[mt][nt][0], acc[mt][nt][1]};
            float2 v1 = {acc[mt][nt][2], acc[mt][nt][3]};
            if (do_rope) {
                const int fi = (col & 127) >> 1;
                const int s0 = (int)(row & (SEQ - 1));
                const int s1 = (int)((row + 8) & (SEQ - 1));
                float c0 = rcs[s0 * 64 + fi], sn0 = rsn[s0 * 64 + fi];
                float c1 = rcs[s1 * 64 + fi], sn1 = rsn[s1 * 64 + fi];
                float2 r0 = {v0.x * c0 - v0.y * sn0, v0.x * sn0 + v0.y * c0};
                float2 r1 = {v1.x * c1 - v1.y * sn1, v1.x * sn1 + v1.y * c1};
                v0 = r0; v1 = r1;
            }
            *(float2*)(C + row * DIM + col)       = v0;
            *(float2*)(C + (row + 8) * DIM + col) = v1;
        }
    }
}

// ============================================================================
// Tensor-core flash attention (tf32 mma.sync): BQ=128, BK=64, 8 warps.
// K double-buffered + V single-buffered cp.async pipeline; in-place tf32
// convert of self-owned chunks. Output written tf32-rounded (feeds WO gemm).
// ============================================================================
#define ABQ 128
#define ABK 64
#define AQS 132
#define AKS 132
#define AVS 136
#define APS 68
#define FA_SMEM ((ABQ*AQS + 2*ABK*AKS + ABK*AVS + 8*16*APS) * 4)   // 204800 B

__global__ __launch_bounds__(256, 1) void flash_mma(const float* __restrict__ Q,
                                                    const float* __restrict__ Kc,
                                                    const float* __restrict__ Vc,
                                                    float* __restrict__ O) {
    extern __shared__ float sm[];
    float* Qs = sm;                              // 128 x 132
    float* Kb = Qs + ABQ * AQS;                  // 2 x (64 x 132)
    float* Vs = Kb + 2 * ABK * AKS;              // 64 x 136
    float* Ps = Vs + ABK * AVS;                  // 8 warps x 16 x 68

    const int t    = threadIdx.x;
    const int w    = t >> 5;
    const int lane = t & 31;
    const int g    = lane >> 2;
    const int q    = lane & 3;
    const int qt   = gridDim.x - 1 - blockIdx.x;   // longest tiles first
    const int h    = blockIdx.y, b = blockIdx.z;
    const float scale = 0.08838834764831845f;      // 1/sqrt(128)

    const uint32_t sKb = smem_u32(Kb);
    const uint32_t sVs = smem_u32(Vs);
    const int nkb = 2 * (qt + 1);

    auto issueK = [&](int kb, int buf) {
        const uint32_t base = sKb + (uint32_t)buf * (ABK * AKS * 4);
        for (int i = t; i < ABK * 32; i += 256) {
            int row = i >> 5, c4 = i & 31;
            size_t gk = ((size_t)((b * SEQ + kb * ABK + row) * NH + h)) * HD + c4 * 4;
            cp16(base + (row * AKS + c4 * 4) * 4, Kc + gk);
        }
    };
    auto issueV = [&](int kb) {
        for (int i = t; i < ABK * 32; i += 256) {
            int row = i >> 5, c4 = i & 31;
            size_t gk = ((size_t)((b * SEQ + kb * ABK + row) * NH + h)) * HD + c4 * 4;
            cp16(sVs + (row * AVS + c4 * 4) * 4, Vc + gk);
        }
    };

    issueK(0, 0); CP_COMMIT();
    issueV(0);    CP_COMMIT();
    for (int i = t; i < ABQ * 32; i += 256) {
        int row = i >> 5, c4 = i & 31;
        const float4 v = *(const float4*)(Q + ((size_t)((b * SEQ + qt * ABQ + row) * NH + h)) * HD + c4 * 4);
        float* d = Qs + row * AQS + c4 * 4;
        d[0] = f2tf_f(v.x); d[1] = f2tf_f(v.y); d[2] = f2tf_f(v.z); d[3] = f2tf_f(v.w);
    }

    float o[16][4];
#pragma unroll
    for (int i = 0; i < 16; i++)
#pragma unroll
        for (int v = 0; v < 4; v++) o[i][v] = 0.f;
    float mA = -INFINITY, mB = -INFINITY, lA = 0.f, lB = 0.f;

    float* Pw = Ps + w * 16 * APS;
    const int r0   = w * 16;
    const int rowA = qt * ABQ + r0 + g;            // rowB = rowA + 8
    __syncthreads();

    for (int kb = 0; kb < nkb; kb++) {
        if (kb + 1 < nkb) issueK(kb + 1, (kb + 1) & 1);
        CP_COMMIT();
        CP_WAIT1();          // K_kb and V_kb (own chunks) landed

        float* Kcur = Kb + (kb & 1) * (ABK * AKS);
        for (int i = t; i < ABK * 32; i += 256) {
            int row = i >> 5, c4 = i & 31;
            float4* pk = (float4*)(Kcur + row * AKS + c4 * 4);
            float4 kv = *pk;
            kv.x = f2tf_f(kv.x); kv.y = f2tf_f(kv.y); kv.z = f2tf_f(kv.z); kv.w = f2tf_f(kv.w);
            *pk = kv;
            float4* pv = (float4*)(Vs + row * AVS + c4 * 4);
            float4 vv = *pv;
            vv.x = f2tf_f(vv.x); vv.y = f2tf_f(vv.y); vv.z = f2tf_f(vv.z); vv.w = f2tf_f(vv.w);
            *pv = vv;
        }
        __syncthreads();

        const bool full_skip = (kb * ABK > qt * ABQ + r0 + 15);
        if (!full_skip) {
            float s[8][4];
#pragma unroll
            for (int i = 0; i < 8; i++)
#pragma unroll
                for (int v = 0; v < 4; v++) s[i][v] = 0.f;
#pragma unroll
            for (int k8 = 0; k8 < 16; k8++) {
                const int kc = k8 * 8 + q;
                uint32_t a[4];
                a[0] = __float_as_uint(Qs[(r0 + g) * AQS + kc]);
                a[1] = __float_as_uint(Qs[(r0 + g + 8) * AQS + kc]);
                a[2] = __float_as_uint(Qs[(r0 + g) * AQS + kc + 4]);
                a[3] = __float_as_uint(Qs[(r0 + g + 8) * AQS + kc + 4]);
#pragma unroll
                for (int nt = 0; nt < 8; nt++) {
                    uint32_t bfr[2];
                    bfr[0] = __float_as_uint(Kcur[(nt * 8 + g) * AKS + kc]);
                    bfr[1] = __float_as_uint(Kcur[(nt * 8 + g) * AKS + kc + 4]);
                    mma16n8k8(s[nt], a, bfr);
                }
            }
            const bool need_mask = (kb * ABK + ABK - 1 > qt * ABQ + r0);
#pragma unroll
            for (int nt = 0; nt < 8; nt++) {
                const int c0 = kb * ABK + nt * 8 + 2 * q;
                s[nt][0] *= scale; s[nt][1] *= scale;
                s[nt][2] *= scale; s[nt][3] *= scale;
                if (need_mask) {
                    if (c0     > rowA)     s[nt][0] = -1e30f;
                    if (c0 + 1 > rowA)     s[nt][1] = -1e30f;
                    if (c0     > rowA + 8) s[nt][2] = -1e30f;
                    if (c0 + 1 > rowA + 8) s[nt][3] = -1e30f;
                }
            }
            float mxA = -INFINITY, mxB = -INFINITY;
#pragma unroll
            for (int nt = 0; nt < 8; nt++) {
                mxA = fmaxf(mxA, fmaxf(s[nt][0], s[nt][1]));
                mxB = fmaxf(mxB, fmaxf(s[nt][2], s[nt][3]));
            }
            mxA = fmaxf(mxA, __shfl_xor_sync(0xffffffffu, mxA, 1));
            mxA = fmaxf(mxA, __shfl_xor_sync(0xffffffffu, mxA, 2));
            mxB = fmaxf(mxB, __shfl_xor_sync(0xffffffffu, mxB, 1));
            mxB = fmaxf(mxB, __shfl_xor_sync(0xffffffffu, mxB, 2));
            const float mnA = fmaxf(mA, mxA), mnB = fmaxf(mB, mxB);
            const float aA = __expf(mA - mnA), aB = __expf(mB - mnB);
            float sumA = 0.f, sumB = 0.f;
#pragma unroll
            for (int nt = 0; nt < 8; nt++) {
                float p0 = __expf(s[nt][0] - mnA), p1 = __expf(s[nt][1] - mnA);
                float p2 = __expf(s[nt][2] - mnB), p3 = __expf(s[nt][3] - mnB);
                sumA += p0 + p1; sumB += p2 + p3;
                float2 pa = {f2tf_f(p0), f2tf_f(p1)};
                float2 pb = {f2tf_f(p2), f2tf_f(p3)};
                *(float2*)(Pw + g * APS + nt * 8 + 2 * q)       = pa;
                *(float2*)(Pw + (g + 8) * APS + nt * 8 + 2 * q) = pb;
            }
            sumA += __shfl_xor_sync(0xffffffffu, sumA, 1);
            sumA += __shfl_xor_sync(0xffffffffu, sumA, 2);
            sumB += __shfl_xor_sync(0xffffffffu, sumB, 1);
            sumB += __shfl_xor_sync(0xffffffffu, sumB, 2);
            lA = lA * aA + sumA;  mA = mnA;
            lB = lB * aB + sumB;  mB = mnB;
#pragma unroll
            for (int nt = 0; nt < 16; nt++) {
                o[nt][0] *= aA; o[nt][1] *= aA;
                o[nt][2] *= aB; o[nt][3] *= aB;
            }
            __syncwarp();
#pragma unroll
            for (int k8 = 0; k8 < 8; k8++) {
                const int kc = k8 * 8 + q;
                uint32_t a[4];
                a[0] = __float_as_uint(Pw[g * APS + kc]);
                a[1] = __float_as_uint(Pw[(g + 8) * APS + kc]);
                a[2] = __float_as_uint(Pw[g * APS + kc + 4]);
                a[3] = __float_as_uint(Pw[(g + 8) * APS + kc + 4]);
#pragma unroll
                for (int nt = 0; nt < 16; nt++) {
                    uint32_t bfr[2];
                    bfr[0] = __float_as_uint(Vs[kc * AVS + nt * 8 + g]);
                    bfr[1] = __float_as_uint(Vs[(kc + 4) * AVS + nt * 8 + g]);
                    mma16n8k8(o[nt], a, bfr);
                }
            }
        }
        __syncthreads();     // everyone done with Vs before refill

        if (kb + 1 < nkb) issueV(kb + 1);
        CP_COMMIT();
    }

    // write tf32-rounded (identical arithmetic: WO mma rounds anyway)
    const float invA = 1.f / lA, invB = 1.f / lB;
    const size_t baseA = ((size_t)((b * SEQ + rowA) * NH + h)) * HD;
    const size_t baseB = baseA + (size_t)8 * NH * HD;
#pragma unroll
    for (int nt = 0; nt < 16; nt++) {
        float2 va = {f2tf_f(o[nt][0] * invA), f2tf_f(o[nt][1] * invA)};
        float2 vb = {f2tf_f(o[nt][2] * invB), f2tf_f(o[nt][3] * invB)};
        *(float2*)(O + baseA + nt * 8 + 2 * q) = va;
        *(float2*)(O + baseB + nt * 8 + 2 * q) = vb;
    }
}

// ============================================================================
// launch
// ============================================================================
extern "C" void kernel_launch(void* const* d_in, const int* in_sizes, int n_in,
                              void* d_out, int out_size) {
    const float* x    = (const float*)d_in[0];
    const float* fcos = (const float*)d_in[1];
    const float* fsin = (const float*)d_in[2];
    // d_in[3] mask, d_in[4] input_idexes, d_in[5] cache_k, d_in[6] cache_v: unused
    const float* wq = (const float*)d_in[7];
    const float* wk = (const float*)d_in[8];
    const float* wv = (const float*)d_in[9];
    const float* wo = (const float*)d_in[10];

    float* out     = (float*)d_out;                               // [B,S,DIM]
    float* cache_k = (float*)d_out + (size_t)NTOK * DIM;          // [B,S,NH,HD]
    float* cache_v = (float*)d_out + (size_t)2 * NTOK * DIM;      // [B,S,NH,HD]

    float* qbuf; cudaGetSymbolAddress((void**)&qbuf, g_q);
    float* abuf; cudaGetSymbolAddress((void**)&abuf, g_att);
    float* xt;   cudaGetSymbolAddress((void**)&xt,   g_xt);
    float* wqt;  cudaGetSymbolAddress((void**)&wqt,  g_wqt);
    float* wkt;  cudaGetSymbolAddress((void**)&wkt,  g_wkt);
    float* wvt;  cudaGetSymbolAddress((void**)&wvt,  g_wvt);
    float* wot;  cudaGetSymbolAddress((void**)&wot,  g_wot);

    cudaFuncSetAttribute(gemm_mma,  cudaFuncAttributeMaxDynamicSharedMemorySize, G_SMEM);
    cudaFuncSetAttribute(flash_mma, cudaFuncAttributeMaxDynamicSharedMemorySize, FA_SMEM);

    const int N8 = NTOK * DIM / 8;         // 8-float groups per 64MB buffer
    const int cb = (N8 + 255) / 256;
    cvt_perm<<<cb, 256>>>((const float4*)x,  (float4*)xt,  N8);
    cvt_perm<<<cb, 256>>>((const float4*)wq, (float4*)wqt, N8);
    cvt_perm<<<cb, 256>>>((const float4*)wk, (float4*)wkt, N8);
    cvt_perm<<<cb, 256>>>((const float4*)wv, (float4*)wvt, N8);
    cvt_perm<<<cb, 256>>>((const float4*)wo, (float4*)wot, N8);

    // fused QKV: z=0 -> Q (rope), z=1 -> K (rope), z=2 -> V
    dim3 gq(DIM / GTN, NTOK / GTM, 3);     // (32, 16, 3)
    gemm_mma<<<gq, 512, G_SMEM>>>(xt, wqt, wkt, wvt, qbuf, cache_k, cache_v, fcos, fsin);

    dim3 fg(SEQ / ABQ, NH, BSZ);           // (16, 32, 2)
    flash_mma<<<fg, 256, FA_SMEM>>>(qbuf, cache_k, cache_v, abuf);

    // permute attention output's K-dim (rounding idempotent), then WO gemm
    cvt_perm<<<cb, 256>>>((const float4*)abuf, (float4*)xt, N8);
    dim3 gw(DIM / GTN, NTOK / GTM, 1);     // (32, 16)
    gemm_mma<<<gw, 512, G_SMEM>>>(xt, wot, wot, wot, out, out, out, nullptr, nullptr);
}

// round 9
// speedup vs baseline: 1.0542x; 1.0542x over previous
#include <cuda_runtime.h>
#include <math.h>
#include <stdint.h>

#define DIM   4096
#define NH    32
#define HD    128
#define BSZ   2
#define SEQ   2048
#define NTOK  (BSZ*SEQ)          // 4096 tokens

// ---------------- scratch (allocation-free: __device__ globals) -------------
__device__ float g_q  [(size_t)NTOK * DIM];   // rotated Q (tf32 bits)
__device__ float g_att[(size_t)NTOK * DIM];   // attention out (tf32 bits)
__device__ float g_xt [(size_t)NTOK * DIM];   // tf32+perm x / reused for abuf-perm
__device__ float g_wqt[(size_t)DIM * DIM];    // tf32+perm weights
__device__ float g_wkt[(size_t)DIM * DIM];
__device__ float g_wvt[(size_t)DIM * DIM];
__device__ float g_wot[(size_t)DIM * DIM];

// ============================================================================
// helpers
// ============================================================================
__device__ __forceinline__ uint32_t smem_u32(const void* p) {
    uint32_t a;
    asm("{ .reg .u64 t; cvta.to.shared.u64 t, %1; cvt.u32.u64 %0, t; }"
        : "=r"(a) : "l"(p));
    return a;
}

__device__ __forceinline__ void cp16(uint32_t dst, const void* src) {
    asm volatile("cp.async.cg.shared.global [%0], [%1], 16;" :: "r"(dst), "l"(src));
}
#define CP_COMMIT() asm volatile("cp.async.commit_group;" ::: "memory")
#define CP_WAIT1()  asm volatile("cp.async.wait_group 1;"  ::: "memory")

__device__ __forceinline__ uint32_t f2tf(float f) {
    uint32_t r;
    asm("cvt.rna.tf32.f32 %0, %1;" : "=r"(r) : "f"(f));
    return r;
}
__device__ __forceinline__ float f2tf_f(float f) { return __uint_as_float(f2tf(f)); }

__device__ __forceinline__ void mma16n8k8(float* c, const uint32_t* a, const uint32_t* b) {
    asm volatile(
        "mma.sync.aligned.m16n8k8.row.col.f32.tf32.tf32.f32 "
        "{%0,%1,%2,%3}, {%4,%5,%6,%7}, {%8,%9}, {%0,%1,%2,%3};"
        : "+f"(c[0]), "+f"(c[1]), "+f"(c[2]), "+f"(c[3])
        : "r"(a[0]), "r"(a[1]), "r"(a[2]), "r"(a[3]), "r"(b[0]), "r"(b[1]));
}

// ============================================================================
// tf32 rounding + k-group permutation pass.
// Each 8-float k-group [a0..a7] stored as [a0,a4,a1,a5,a2,a6,a3,a7] so the
// (kc, kc+4) mma fragment pair is one aligned float2 in smem.
// ============================================================================
__global__ __launch_bounds__(256) void cvt_perm(const float4* __restrict__ in,
                                                float4* __restrict__ out, int n8) {
    int i = blockIdx.x * blockDim.x + threadIdx.x;
    if (i < n8) {
        float4 a = in[2 * i], b = in[2 * i + 1];
        float4 o0 = {f2tf_f(a.x), f2tf_f(b.x), f2tf_f(a.y), f2tf_f(b.y)};
        float4 o1 = {f2tf_f(a.z), f2tf_f(b.z), f2tf_f(a.w), f2tf_f(b.w)};
        out[2 * i]     = o0;
        out[2 * i + 1] = o1;
    }
}

// ============================================================================
// tf32 mma.sync GEMM (NT), cvt-free, float2 fragment loads (permuted K).
// C[m,n] = sum_k A[m,k]*B[n,k];  M=NTOK, N=K=4096
// CTA 256x128, 8 warps (4x2), warp tile 64x64, BK=32, 3-stage cp.async pipe.
// round_out: store outputs tf32-rounded (QKV path — flash re-rounds anyway).
// blockIdx.z selects (B, C, rope) — fused QKV in one launch.
// ============================================================================
#define GTM 256
#define GTN 128
#define GBK 32
#define GTS 40
#define GST 3
#define GNKI (DIM / GBK)                                   // 128
#define G_STAGE ((GTM + GTN) * GTS)                        // floats per stage
#define G_SMEM (GST * G_STAGE * 4)                         // 184320 B

__global__ __launch_bounds__(256, 1) void gemm_mma(
    const float* __restrict__ A,
    const float* __restrict__ B0, const float* __restrict__ B1, const float* __restrict__ B2,
    float* __restrict__ C0, float* __restrict__ C1, float* __restrict__ C2,
    const float* __restrict__ rcs, const float* __restrict__ rsn, int round_out) {
    extern __shared__ float smf[];

    const int z = blockIdx.z;
    const float* B = (z == 0) ? B0 : ((z == 1) ? B1 : B2);
    float*       C = (z == 0) ? C0 : ((z == 1) ? C1 : C2);
    const bool do_rope = (rcs != nullptr) && (z < 2);

    const int t    = threadIdx.x;
    const int lane = t & 31;
    const int w    = t >> 5;
    const int wm   = w >> 1;          // 0..3
    const int wn   = w & 1;           // 0..1
    const int g    = lane >> 2;       // 0..7
    const int q    = lane & 3;        // 0..3
    const int bm   = blockIdx.y, bn = blockIdx.x;

    const uint32_t sS = smem_u32(smf);
    const int lr  = t >> 3;           // 0..31
    const int lc4 = (t & 7) * 4;      // 0,4,...,28
    const float* Agp = A + (size_t)(bm * GTM + lr) * DIM + lc4;
    const float* Bgp = B + (size_t)(bn * GTN + lr) * DIM + lc4;

    float acc[4][8][4];
#pragma unroll
    for (int i = 0; i < 4; i++)
#pragma unroll
        for (int j = 0; j < 8; j++)
#pragma unroll
            for (int v = 0; v < 4; v++) acc[i][j][v] = 0.f;

    // prologue: stages 0..GST-2
#pragma unroll
    for (int s = 0; s < GST - 1; s++) {
        const int k0 = s * GBK;
        const uint32_t dA = sS + s * (G_STAGE * 4);
        const uint32_t dB = dA + GTM * GTS * 4;
#pragma unroll
        for (int j = 0; j < 8; j++)
            cp16(dA + ((lr + j * 32) * GTS + lc4) * 4, Agp + (size_t)(j * 32) * DIM + k0);
#pragma unroll
        for (int j = 0; j < 4; j++)
            cp16(dB + ((lr + j * 32) * GTS + lc4) * 4, Bgp + (size_t)(j * 32) * DIM + k0);
        CP_COMMIT();
    }

    for (int i = 0; i < GNKI; i++) {
        CP_WAIT1();
        __syncthreads();

        if (i + GST - 1 < GNKI) {
            const int st = (i + GST - 1) % GST;
            const int k0 = (i + GST - 1) * GBK;
            const uint32_t dA = sS + st * (G_STAGE * 4);
            const uint32_t dB = dA + GTM * GTS * 4;
#pragma unroll
            for (int j = 0; j < 8; j++)
                cp16(dA + ((lr + j * 32) * GTS + lc4) * 4, Agp + (size_t)(j * 32) * DIM + k0);
#pragma unroll
            for (int j = 0; j < 4; j++)
                cp16(dB + ((lr + j * 32) * GTS + lc4) * 4, Bgp + (size_t)(j * 32) * DIM + k0);
        }
        CP_COMMIT();   // empty in tail: keeps group accounting valid

        const float* Ab = smf + (i % GST) * G_STAGE;
        const float* Bb = Ab + GTM * GTS;
#pragma unroll
        for (int k8 = 0; k8 < 4; k8++) {
            const int ks = k8 * 8 + 2 * q;        // permuted slot of (kc, kc+4)
            uint32_t af[4][4], bf[8][2];
#pragma unroll
            for (int mt = 0; mt < 4; mt++) {
                const int r0 = wm * 64 + mt * 16 + g;
                float2 u0 = *(const float2*)(Ab + r0 * GTS + ks);
                float2 u1 = *(const float2*)(Ab + (r0 + 8) * GTS + ks);
                af[mt][0] = __float_as_uint(u0.x);
                af[mt][1] = __float_as_uint(u1.x);
                af[mt][2] = __float_as_uint(u0.y);
                af[mt][3] = __float_as_uint(u1.y);
            }
#pragma unroll
            for (int nt = 0; nt < 8; nt++) {
                const int c0 = wn * 64 + nt * 8 + g;
                float2 v = *(const float2*)(Bb + c0 * GTS + ks);
                bf[nt][0] = __float_as_uint(v.x);
                bf[nt][1] = __float_as_uint(v.y);
            }
#pragma unroll
            for (int mt = 0; mt < 4; mt++)
#pragma unroll
                for (int nt = 0; nt < 8; nt++)
                    mma16n8k8(acc[mt][nt], af[mt], bf[nt]);
        }
    }

    // epilogue (fused RoPE for Q/K; optional tf32 rounding of stores)
#pragma unroll
    for (int mt = 0; mt < 4; mt++) {
        const size_t row = (size_t)bm * GTM + wm * 64 + mt * 16 + g;
#pragma unroll
        for (int nt = 0; nt < 8; nt++) {
            const int col = bn * GTN + wn * 64 + nt * 8 + q * 2;
            float2 v0 = {acc[mt][nt][0], acc[mt][nt][1]};
            float2 v1 = {acc[mt][nt][2], acc[mt][nt][3]};
            if (do_rope) {
                const int fi = (col & 127) >> 1;
                const int s0 = (int)(row & (SEQ - 1));
                const int s1 = (int)((row + 8) & (SEQ - 1));
                float c0 = rcs[s0 * 64 + fi], sn0 = rsn[s0 * 64 + fi];
                float c1 = rcs[s1 * 64 + fi], sn1 = rsn[s1 * 64 + fi];
                float2 r0 = {v0.x * c0 - v0.y * sn0, v0.x * sn0 + v0.y * c0};
                float2 r1 = {v1.x * c1 - v1.y * sn1, v1.x * sn1 + v1.y * c1};
                v0 = r0; v1 = r1;
            }
            if (round_out) {
                v0.x = f2tf_f(v0.x); v0.y = f2tf_f(v0.y);
                v1.x = f2tf_f(v1.x); v1.y = f2tf_f(v1.y);
            }
            *(float2*)(C + row * DIM + col)       = v0;
            *(float2*)(C + (row + 8) * DIM + col) = v1;
        }
    }
}

// ============================================================================
// Tensor-core flash attention (tf32 mma.sync): BQ=128, BK=64, 8 warps.
// All inputs (Q/K/V) are pre-rounded tf32 bits in global — NO convert stage.
// K double-buffered + V single-buffered + Q via cp.async.
// ============================================================================
#define ABQ 128
#define ABK 64
#define AQS 132
#define AKS 132
#define AVS 136
#define APS 68
#define FA_SMEM ((ABQ*AQS + 2*ABK*AKS + ABK*AVS + 8*16*APS) * 4)   // 204800 B

__global__ __launch_bounds__(256, 1) void flash_mma(const float* __restrict__ Q,
                                                    const float* __restrict__ Kc,
                                                    const float* __restrict__ Vc,
                                                    float* __restrict__ O) {
    extern __shared__ float sm[];
    float* Qs = sm;                              // 128 x 132
    float* Kb = Qs + ABQ * AQS;                  // 2 x (64 x 132)
    float* Vs = Kb + 2 * ABK * AKS;              // 64 x 136
    float* Ps = Vs + ABK * AVS;                  // 8 warps x 16 x 68

    const int t    = threadIdx.x;
    const int w    = t >> 5;
    const int lane = t & 31;
    const int g    = lane >> 2;
    const int q    = lane & 3;
    const int qt   = gridDim.x - 1 - blockIdx.x;   // longest tiles first
    const int h    = blockIdx.y, b = blockIdx.z;
    const float scale = 0.08838834764831845f;      // 1/sqrt(128)

    const uint32_t sQs = smem_u32(Qs);
    const uint32_t sKb = smem_u32(Kb);
    const uint32_t sVs = smem_u32(Vs);
    const int nkb = 2 * (qt + 1);

    auto issueK = [&](int kb, int buf) {
        const uint32_t base = sKb + (uint32_t)buf * (ABK * AKS * 4);
        for (int i = t; i < ABK * 32; i += 256) {
            int row = i >> 5, c4 = i & 31;
            size_t gk = ((size_t)((b * SEQ + kb * ABK + row) * NH + h)) * HD + c4 * 4;
            cp16(base + (row * AKS + c4 * 4) * 4, Kc + gk);
        }
    };
    auto issueV = [&](int kb) {
        for (int i = t; i < ABK * 32; i += 256) {
            int row = i >> 5, c4 = i & 31;
            size_t gk = ((size_t)((b * SEQ + kb * ABK + row) * NH + h)) * HD + c4 * 4;
            cp16(sVs + (row * AVS + c4 * 4) * 4, Vc + gk);
        }
    };

    // prologue: group0 = K0, group1 = {V0, Q}
    issueK(0, 0); CP_COMMIT();
    issueV(0);
    for (int i = t; i < ABQ * 32; i += 256) {
        int row = i >> 5, c4 = i & 31;
        size_t gq = ((size_t)((b * SEQ + qt * ABQ + row) * NH + h)) * HD + c4 * 4;
        cp16(sQs + (row * AQS + c4 * 4) * 4, Q + gq);
    }
    CP_COMMIT();

    float o[16][4];
#pragma unroll
    for (int i = 0; i < 16; i++)
#pragma unroll
        for (int v = 0; v < 4; v++) o[i][v] = 0.f;
    float mA = -INFINITY, mB = -INFINITY, lA = 0.f, lB = 0.f;

    float* Pw = Ps + w * 16 * APS;
    const int r0   = w * 16;
    const int rowA = qt * ABQ + r0 + g;            // rowB = rowA + 8

    for (int kb = 0; kb < nkb; kb++) {
        if (kb + 1 < nkb) issueK(kb + 1, (kb + 1) & 1);
        CP_COMMIT();
        CP_WAIT1();          // K_kb, V_kb, Q landed
        __syncthreads();

        float* Kcur = Kb + (kb & 1) * (ABK * AKS);
        const bool full_skip = (kb * ABK > qt * ABQ + r0 + 15);
        if (!full_skip) {
            float s[8][4];
#pragma unroll
            for (int i = 0; i < 8; i++)
#pragma unroll
                for (int v = 0; v < 4; v++) s[i][v] = 0.f;
#pragma unroll
            for (int k8 = 0; k8 < 16; k8++) {
                const int kc = k8 * 8 + q;
                uint32_t a[4];
                a[0] = __float_as_uint(Qs[(r0 + g) * AQS + kc]);
                a[1] = __float_as_uint(Qs[(r0 + g + 8) * AQS + kc]);
                a[2] = __float_as_uint(Qs[(r0 + g) * AQS + kc + 4]);
                a[3] = __float_as_uint(Qs[(r0 + g + 8) * AQS + kc + 4]);
#pragma unroll
                for (int nt = 0; nt < 8; nt++) {
                    uint32_t bfr[2];
                    bfr[0] = __float_as_uint(Kcur[(nt * 8 + g) * AKS + kc]);
                    bfr[1] = __float_as_uint(Kcur[(nt * 8 + g) * AKS + kc + 4]);
                    mma16n8k8(s[nt], a, bfr);
                }
            }
            const bool need_mask = (kb * ABK + ABK - 1 > qt * ABQ + r0);
#pragma unroll
            for (int nt = 0; nt < 8; nt++) {
                const int c0 = kb * ABK + nt * 8 + 2 * q;
                s[nt][0] *= scale; s[nt][1] *= scale;
                s[nt][2] *= scale; s[nt][3] *= scale;
                if (need_mask) {
                    if (c0     > rowA)     s[nt][0] = -1e30f;
                    if (c0 + 1 > rowA)     s[nt][1] = -1e30f;
                    if (c0     > rowA + 8) s[nt][2] = -1e30f;
                    if (c0 + 1 > rowA + 8) s[nt][3] = -1e30f;
                }
            }
            float mxA = -INFINITY, mxB = -INFINITY;
#pragma unroll
            for (int nt = 0; nt < 8; nt++) {
                mxA = fmaxf(mxA, fmaxf(s[nt][0], s[nt][1]));
                mxB = fmaxf(mxB, fmaxf(s[nt][2], s[nt][3]));
            }
            mxA = fmaxf(mxA, __shfl_xor_sync(0xffffffffu, mxA, 1));
            mxA = fmaxf(mxA, __shfl_xor_sync(0xffffffffu, mxA, 2));
            mxB = fmaxf(mxB, __shfl_xor_sync(0xffffffffu, mxB, 1));
            mxB = fmaxf(mxB, __shfl_xor_sync(0xffffffffu, mxB, 2));
            const float mnA = fmaxf(mA, mxA), mnB = fmaxf(mB, mxB);
            const float aA = __expf(mA - mnA), aB = __expf(mB - mnB);
            float sumA = 0.f, sumB = 0.f;
#pragma unroll
            for (int nt = 0; nt < 8; nt++) {
                float p0 = __expf(s[nt][0] - mnA), p1 = __expf(s[nt][1] - mnA);
                float p2 = __expf(s[nt][2] - mnB), p3 = __expf(s[nt][3] - mnB);
                sumA += p0 + p1; sumB += p2 + p3;
                float2 pa = {f2tf_f(p0), f2tf_f(p1)};
                float2 pb = {f2tf_f(p2), f2tf_f(p3)};
                *(float2*)(Pw + g * APS + nt * 8 + 2 * q)       = pa;
                *(float2*)(Pw + (g + 8) * APS + nt * 8 + 2 * q) = pb;
            }
            sumA += __shfl_xor_sync(0xffffffffu, sumA, 1);
            sumA += __shfl_xor_sync(0xffffffffu, sumA, 2);
            sumB += __shfl_xor_sync(0xffffffffu, sumB, 1);
            sumB += __shfl_xor_sync(0xffffffffu, sumB, 2);
            lA = lA * aA + sumA;  mA = mnA;
            lB = lB * aB + sumB;  mB = mnB;
#pragma unroll
            for (int nt = 0; nt < 16; nt++) {
                o[nt][0] *= aA; o[nt][1] *= aA;
                o[nt][2] *= aB; o[nt][3] *= aB;
            }
            __syncwarp();
#pragma unroll
            for (int k8 = 0; k8 < 8; k8++) {
                const int kc = k8 * 8 + q;
                uint32_t a[4];
                a[0] = __float_as_uint(Pw[g * APS + kc]);
                a[1] = __float_as_uint(Pw[(g + 8) * APS + kc]);
                a[2] = __float_as_uint(Pw[g * APS + kc + 4]);
                a[3] = __float_as_uint(Pw[(g + 8) * APS + kc + 4]);
#pragma unroll
                for (int nt = 0; nt < 16; nt++) {
                    uint32_t bfr[2];
                    bfr[0] = __float_as_uint(Vs[kc * AVS + nt * 8 + g]);
                    bfr[1] = __float_as_uint(Vs[(kc + 4) * AVS + nt * 8 + g]);
                    mma16n8k8(o[nt], a, bfr);
                }
            }
        }
        __syncthreads();     // everyone done with Vs before refill

        if (kb + 1 < nkb) issueV(kb + 1);
        CP_COMMIT();
    }

    // write tf32-rounded (identical arithmetic: WO mma rounds anyway)
    const float invA = 1.f / lA, invB = 1.f / lB;
    const size_t baseA = ((size_t)((b * SEQ + rowA) * NH + h)) * HD;
    const size_t baseB = baseA + (size_t)8 * NH * HD;
#pragma unroll
    for (int nt = 0; nt < 16; nt++) {
        float2 va = {f2tf_f(o[nt][0] * invA), f2tf_f(o[nt][1] * invA)};
        float2 vb = {f2tf_f(o[nt][2] * invB), f2tf_f(o[nt][3] * invB)};
        *(float2*)(O + baseA + nt * 8 + 2 * q) = va;
        *(float2*)(O + baseB + nt * 8 + 2 * q) = vb;
    }
}

// ============================================================================
// launch
// ============================================================================
extern "C" void kernel_launch(void* const* d_in, const int* in_sizes, int n_in,
                              void* d_out, int out_size) {
    const float* x    = (const float*)d_in[0];
    const float* fcos = (const float*)d_in[1];
    const float* fsin = (const float*)d_in[2];
    // d_in[3] mask, d_in[4] input_idexes, d_in[5] cache_k, d_in[6] cache_v: unused
    const float* wq = (const float*)d_in[7];
    const float* wk = (const float*)d_in[8];
    const float* wv = (const float*)d_in[9];
    const float* wo = (const float*)d_in[10];

    float* out     = (float*)d_out;                               // [B,S,DIM]
    float* cache_k = (float*)d_out + (size_t)NTOK * DIM;          // [B,S,NH,HD]
    float* cache_v = (float*)d_out + (size_t)2 * NTOK * DIM;      // [B,S,NH,HD]

    float* qbuf; cudaGetSymbolAddress((void**)&qbuf, g_q);
    float* abuf; cudaGetSymbolAddress((void**)&abuf, g_att);
    float* xt;   cudaGetSymbolAddress((void**)&xt,   g_xt);
    float* wqt;  cudaGetSymbolAddress((void**)&wqt,  g_wqt);
    float* wkt;  cudaGetSymbolAddress((void**)&wkt,  g_wkt);
    float* wvt;  cudaGetSymbolAddress((void**)&wvt,  g_wvt);
    float* wot;  cudaGetSymbolAddress((void**)&wot,  g_wot);

    cudaFuncSetAttribute(gemm_mma,  cudaFuncAttributeMaxDynamicSharedMemorySize, G_SMEM);
    cudaFuncSetAttribute(flash_mma, cudaFuncAttributeMaxDynamicSharedMemorySize, FA_SMEM);

    const int N8 = NTOK * DIM / 8;         // 8-float groups per 64MB buffer
    const int cb = (N8 + 255) / 256;
    cvt_perm<<<cb, 256>>>((const float4*)x,  (float4*)xt,  N8);
    cvt_perm<<<cb, 256>>>((const float4*)wq, (float4*)wqt, N8);
    cvt_perm<<<cb, 256>>>((const float4*)wk, (float4*)wkt, N8);
    cvt_perm<<<cb, 256>>>((const float4*)wv, (float4*)wvt, N8);
    cvt_perm<<<cb, 256>>>((const float4*)wo, (float4*)wot, N8);

    // fused QKV: z=0 -> Q (rope), z=1 -> K (rope), z=2 -> V; outputs tf32-rounded
    dim3 gq(DIM / GTN, NTOK / GTM, 3);     // (32, 16, 3)
    gemm_mma<<<gq, 256, G_SMEM>>>(xt, wqt, wkt, wvt, qbuf, cache_k, cache_v,
                                  fcos, fsin, 1);

    dim3 fg(SEQ / ABQ, NH, BSZ);           // (16, 32, 2)
    flash_mma<<<fg, 256, FA_SMEM>>>(qbuf, cache_k, cache_v, abuf);

    // permute attention output's K-dim (rounding idempotent), then WO gemm
    cvt_perm<<<cb, 256>>>((const float4*)abuf, (float4*)xt, N8);
    dim3 gw(DIM / GTN, NTOK / GTM, 1);     // (32, 16)
    gemm_mma<<<gw, 256, G_SMEM>>>(xt, wot, wot, wot, out, out, out,
                                  nullptr, nullptr, 0);
}

// round 10
// speedup vs baseline: 1.5953x; 1.5133x over previous
#include <cuda_runtime.h>
#include <cuda_fp16.h>
#include <math.h>
#include <stdint.h>

#define DIM   4096
#define NH    32
#define HD    128
#define BSZ   2
#define SEQ   2048
#define NTOK  (BSZ*SEQ)          // 4096 tokens

// ---------------- scratch (allocation-free: __device__ globals) -------------
__device__ float  g_q  [(size_t)NTOK * DIM];   // rotated Q (tf32 bits, fp32 storage)
__device__ float  g_att[(size_t)NTOK * DIM];   // attention out (tf32 bits)
__device__ __half g_xt [(size_t)NTOK * DIM];   // fp16+perm x / reused for abuf-perm
__device__ __half g_wqt[(size_t)DIM * DIM];    // fp16+perm weights
__device__ __half g_wkt[(size_t)DIM * DIM];
__device__ __half g_wvt[(size_t)DIM * DIM];
__device__ __half g_wot[(size_t)DIM * DIM];

// ============================================================================
// helpers
// ============================================================================
__device__ __forceinline__ uint32_t smem_u32(const void* p) {
    uint32_t a;
    asm("{ .reg .u64 t; cvta.to.shared.u64 t, %1; cvt.u32.u64 %0, t; }"
        : "=r"(a) : "l"(p));
    return a;
}

__device__ __forceinline__ void cp16(uint32_t dst, const void* src) {
    asm volatile("cp.async.cg.shared.global [%0], [%1], 16;" :: "r"(dst), "l"(src));
}
#define CP_COMMIT() asm volatile("cp.async.commit_group;" ::: "memory")
#define CP_WAIT1()  asm volatile("cp.async.wait_group 1;"  ::: "memory")
#define CP_WAIT2()  asm volatile("cp.async.wait_group 2;"  ::: "memory")

__device__ __forceinline__ uint32_t f2tf(float f) {
    uint32_t r;
    asm("cvt.rna.tf32.f32 %0, %1;" : "=r"(r) : "f"(f));
    return r;
}
__device__ __forceinline__ float f2tf_f(float f) { return __uint_as_float(f2tf(f)); }

__device__ __forceinline__ uint32_t pack_h2(float a, float b) {
    __half2 h = __floats2half2_rn(a, b);
    return *(uint32_t*)&h;
}

// tf32 m16n8k8 (flash attention)
__device__ __forceinline__ void mma16n8k8(float* c, const uint32_t* a, const uint32_t* b) {
    asm volatile(
        "mma.sync.aligned.m16n8k8.row.col.f32.tf32.tf32.f32 "
        "{%0,%1,%2,%3}, {%4,%5,%6,%7}, {%8,%9}, {%0,%1,%2,%3};"
        : "+f"(c[0]), "+f"(c[1]), "+f"(c[2]), "+f"(c[3])
        : "r"(a[0]), "r"(a[1]), "r"(a[2]), "r"(a[3]), "r"(b[0]), "r"(b[1]));
}

// fp16 m16n8k16 (GEMMs) — 2x FLOPs per instruction vs tf32 k8
__device__ __forceinline__ void mma16n8k16h(float* c, const uint32_t* a, const uint32_t* b) {
    asm volatile(
        "mma.sync.aligned.m16n8k16.row.col.f32.f16.f16.f32 "
        "{%0,%1,%2,%3}, {%4,%5,%6,%7}, {%8,%9}, {%0,%1,%2,%3};"
        : "+f"(c[0]), "+f"(c[1]), "+f"(c[2]), "+f"(c[3])
        : "r"(a[0]), "r"(a[1]), "r"(a[2]), "r"(a[3]), "r"(b[0]), "r"(b[1]));
}

// ============================================================================
// fp32 -> fp16 (rne) + k-group permutation.
// Each 16-float k-group [l0..l15] is stored as halves in order
// [l0,l1,l8,l9, l2,l3,l10,l11, l4,l5,l12,l13, l6,l7,l14,l15]:
// thread q's m16n8k16 fragment halves (2q,2q+1,2q+8,2q+9) = one aligned float2.
// ============================================================================
__global__ __launch_bounds__(256) void cvt_h(const float4* __restrict__ in,
                                             uint4* __restrict__ out, int n16) {
    int i = blockIdx.x * blockDim.x + threadIdx.x;
    if (i < n16) {
        float4 v0 = in[4 * i], v1 = in[4 * i + 1], v2 = in[4 * i + 2], v3 = in[4 * i + 3];
        uint4 o0, o1;
        o0.x = pack_h2(v0.x, v0.y); o0.y = pack_h2(v2.x, v2.y);
        o0.z = pack_h2(v0.z, v0.w); o0.w = pack_h2(v2.z, v2.w);
        o1.x = pack_h2(v1.x, v1.y); o1.y = pack_h2(v3.x, v3.y);
        o1.z = pack_h2(v1.z, v1.w); o1.w = pack_h2(v3.z, v3.w);
        out[2 * i]     = o0;
        out[2 * i + 1] = o1;
    }
}

// ============================================================================
// fp16 mma.sync GEMM (NT): C[m,n] = sum_k A[m,k]*B[n,k];  M=NTOK, N=K=4096
// CTA 256x128, 8 warps (4x2), warp tile 64x64, BK=32 halves (2 k16 steps),
// 4-stage cp.async pipeline. smem row stride 48 halves (96B): fragment LDS.64
// phases map g 0..3 -> disjoint bank spans {0,24,16,8}.
// round_out: store outputs tf32-rounded (QKV path — flash runs tf32 mma).
// blockIdx.z selects (B, C, rope) — fused QKV in one launch.
// ============================================================================
#define GTM 256
#define GTN 128
#define GBK 32
#define GTS 48
#define GST 4
#define GNKI (DIM / GBK)                                   // 128
#define G_STAGE ((GTM + GTN) * GTS)                        // halves per stage
#define G_SMEM (GST * G_STAGE * 2)                         // 147456 B

__global__ __launch_bounds__(256, 1) void gemm_mma(
    const __half* __restrict__ A,
    const __half* __restrict__ B0, const __half* __restrict__ B1, const __half* __restrict__ B2,
    float* __restrict__ C0, float* __restrict__ C1, float* __restrict__ C2,
    const float* __restrict__ rcs, const float* __restrict__ rsn, int round_out) {
    extern __shared__ __half smh[];

    const int z = blockIdx.z;
    const __half* B = (z == 0) ? B0 : ((z == 1) ? B1 : B2);
    float*        C = (z == 0) ? C0 : ((z == 1) ? C1 : C2);
    const bool do_rope = (rcs != nullptr) && (z < 2);

    const int t    = threadIdx.x;
    const int lane = t & 31;
    const int w    = t >> 5;
    const int wm   = w >> 1;          // 0..3
    const int wn   = w & 1;           // 0..1
    const int g    = lane >> 2;       // 0..7
    const int q    = lane & 3;        // 0..3
    const int bm   = blockIdx.y, bn = blockIdx.x;

    const uint32_t sS = smem_u32(smh);
    const int lr  = t >> 2;           // 0..63
    const int lc8 = (t & 3) * 8;      // half offset 0,8,16,24
    const __half* Agp = A + (size_t)(bm * GTM + lr) * DIM + lc8;
    const __half* Bgp = B + (size_t)(bn * GTN + lr) * DIM + lc8;

    float acc[4][8][4];
#pragma unroll
    for (int i = 0; i < 4; i++)
#pragma unroll
        for (int j = 0; j < 8; j++)
#pragma unroll
            for (int v = 0; v < 4; v++) acc[i][j][v] = 0.f;

    // prologue: stages 0..GST-2
#pragma unroll
    for (int s = 0; s < GST - 1; s++) {
        const int k0 = s * GBK;
        const uint32_t dA = sS + s * (G_STAGE * 2);
        const uint32_t dB = dA + GTM * GTS * 2;
#pragma unroll
        for (int j = 0; j < 4; j++)
            cp16(dA + ((lr + j * 64) * GTS + lc8) * 2, Agp + (size_t)(j * 64) * DIM + k0);
#pragma unroll
        for (int j = 0; j < 2; j++)
            cp16(dB + ((lr + j * 64) * GTS + lc8) * 2, Bgp + (size_t)(j * 64) * DIM + k0);
        CP_COMMIT();
    }

    for (int i = 0; i < GNKI; i++) {
        CP_WAIT2();
        __syncthreads();

        if (i + GST - 1 < GNKI) {
            const int st = (i + GST - 1) & (GST - 1);
            const int k0 = (i + GST - 1) * GBK;
            const uint32_t dA = sS + st * (G_STAGE * 2);
            const uint32_t dB = dA + GTM * GTS * 2;
#pragma unroll
            for (int j = 0; j < 4; j++)
                cp16(dA + ((lr + j * 64) * GTS + lc8) * 2, Agp + (size_t)(j * 64) * DIM + k0);
#pragma unroll
            for (int j = 0; j < 2; j++)
                cp16(dB + ((lr + j * 64) * GTS + lc8) * 2, Bgp + (size_t)(j * 64) * DIM + k0);
        }
        CP_COMMIT();   // empty in tail: keeps group accounting valid

        const __half* Ab = smh + (i & (GST - 1)) * G_STAGE;
        const __half* Bb = Ab + GTM * GTS;
#pragma unroll
        for (int s = 0; s < 2; s++) {
            const int ks = s * 16 + 4 * q;        // permuted slot of (2q,2q+1,2q+8,2q+9)
            uint32_t af[4][4], bf[8][2];
#pragma unroll
            for (int mt = 0; mt < 4; mt++) {
                const int r0 = wm * 64 + mt * 16 + g;
                float2 u0 = *(const float2*)(Ab + r0 * GTS + ks);
                float2 u1 = *(const float2*)(Ab + (r0 + 8) * GTS + ks);
                af[mt][0] = __float_as_uint(u0.x);   // (row g,   k 2q..2q+1)
                af[mt][1] = __float_as_uint(u1.x);   // (row g+8, k 2q..2q+1)
                af[mt][2] = __float_as_uint(u0.y);   // (row g,   k 2q+8..2q+9)
                af[mt][3] = __float_as_uint(u1.y);   // (row g+8, k 2q+8..2q+9)
            }
#pragma unroll
            for (int nt = 0; nt < 8; nt++) {
                const int c0 = wn * 64 + nt * 8 + g;
                float2 v = *(const float2*)(Bb + c0 * GTS + ks);
                bf[nt][0] = __float_as_uint(v.x);
                bf[nt][1] = __float_as_uint(v.y);
            }
#pragma unroll
            for (int mt = 0; mt < 4; mt++)
#pragma unroll
                for (int nt = 0; nt < 8; nt++)
                    mma16n8k16h(acc[mt][nt], af[mt], bf[nt]);
        }
    }

    // epilogue (fused RoPE for Q/K; optional tf32 rounding of stores)
#pragma unroll
    for (int mt = 0; mt < 4; mt++) {
        const size_t row = (size_t)bm * GTM + wm * 64 + mt * 16 + g;
#pragma unroll
        for (int nt = 0; nt < 8; nt++) {
            const int col = bn * GTN + wn * 64 + nt * 8 + q * 2;
            float2 v0 = {acc[mt][nt][0], acc[mt][nt][1]};
            float2 v1 = {acc[mt][nt][2], acc[mt][nt][3]};
            if (do_rope) {
                const int fi = (col & 127) >> 1;
                const int s0 = (int)(row & (SEQ - 1));
                const int s1 = (int)((row + 8) & (SEQ - 1));
                float c0 = rcs[s0 * 64 + fi], sn0 = rsn[s0 * 64 + fi];
                float c1 = rcs[s1 * 64 + fi], sn1 = rsn[s1 * 64 + fi];
                float2 r0 = {v0.x * c0 - v0.y * sn0, v0.x * sn0 + v0.y * c0};
                float2 r1 = {v1.x * c1 - v1.y * sn1, v1.x * sn1 + v1.y * c1};
                v0 = r0; v1 = r1;
            }
            if (round_out) {
                v0.x = f2tf_f(v0.x); v0.y = f2tf_f(v0.y);
                v1.x = f2tf_f(v1.x); v1.y = f2tf_f(v1.y);
            }
            *(float2*)(C + row * DIM + col)       = v0;
            *(float2*)(C + (row + 8) * DIM + col) = v1;
        }
    }
}

// ============================================================================
// Tensor-core flash attention (tf32 mma.sync): BQ=128, BK=64, 8 warps.
// All inputs (Q/K/V) are pre-rounded tf32 bits in global — NO convert stage.
// K double-buffered + V single-buffered + Q via cp.async.
// ============================================================================
#define ABQ 128
#define ABK 64
#define AQS 132
#define AKS 132
#define AVS 136
#define APS 68
#define FA_SMEM ((ABQ*AQS + 2*ABK*AKS + ABK*AVS + 8*16*APS) * 4)   // 204800 B

__global__ __launch_bounds__(256, 1) void flash_mma(const float* __restrict__ Q,
                                                    const float* __restrict__ Kc,
                                                    const float* __restrict__ Vc,
                                                    float* __restrict__ O) {
    extern __shared__ float sm[];
    float* Qs = sm;                              // 128 x 132
    float* Kb = Qs + ABQ * AQS;                  // 2 x (64 x 132)
    float* Vs = Kb + 2 * ABK * AKS;              // 64 x 136
    float* Ps = Vs + ABK * AVS;                  // 8 warps x 16 x 68

    const int t    = threadIdx.x;
    const int w    = t >> 5;
    const int lane = t & 31;
    const int g    = lane >> 2;
    const int q    = lane & 3;
    const int qt   = gridDim.x - 1 - blockIdx.x;   // longest tiles first
    const int h    = blockIdx.y, b = blockIdx.z;
    const float scale = 0.08838834764831845f;      // 1/sqrt(128)

    const uint32_t sQs = smem_u32(Qs);
    const uint32_t sKb = smem_u32(Kb);
    const uint32_t sVs = smem_u32(Vs);
    const int nkb = 2 * (qt + 1);

    auto issueK = [&](int kb, int buf) {
        const uint32_t base = sKb + (uint32_t)buf * (ABK * AKS * 4);
        for (int i = t; i < ABK * 32; i += 256) {
            int row = i >> 5, c4 = i & 31;
            size_t gk = ((size_t)((b * SEQ + kb * ABK + row) * NH + h)) * HD + c4 * 4;
            cp16(base + (row * AKS + c4 * 4) * 4, Kc + gk);
        }
    };
    auto issueV = [&](int kb) {
        for (int i = t; i < ABK * 32; i += 256) {
            int row = i >> 5, c4 = i & 31;
            size_t gk = ((size_t)((b * SEQ + kb * ABK + row) * NH + h)) * HD + c4 * 4;
            cp16(sVs + (row * AVS + c4 * 4) * 4, Vc + gk);
        }
    };

    // prologue: group0 = K0, group1 = {V0, Q}
    issueK(0, 0); CP_COMMIT();
    issueV(0);
    for (int i = t; i < ABQ * 32; i += 256) {
        int row = i >> 5, c4 = i & 31;
        size_t gq = ((size_t)((b * SEQ + qt * ABQ + row) * NH + h)) * HD + c4 * 4;
        cp16(sQs + (row * AQS + c4 * 4) * 4, Q + gq);
    }
    CP_COMMIT();

    float o[16][4];
#pragma unroll
    for (int i = 0; i < 16; i++)
#pragma unroll
        for (int v = 0; v < 4; v++) o[i][v] = 0.f;
    float mA = -INFINITY, mB = -INFINITY, lA = 0.f, lB = 0.f;

    float* Pw = Ps + w * 16 * APS;
    const int r0   = w * 16;
    const int rowA = qt * ABQ + r0 + g;            // rowB = rowA + 8

    for (int kb = 0; kb < nkb; kb++) {
        if (kb + 1 < nkb) issueK(kb + 1, (kb + 1) & 1);
        CP_COMMIT();
        CP_WAIT1();          // K_kb, V_kb, Q landed
        __syncthreads();

        float* Kcur = Kb + (kb & 1) * (ABK * AKS);
        const bool full_skip = (kb * ABK > qt * ABQ + r0 + 15);
        if (!full_skip) {
            float s[8][4];
#pragma unroll
            for (int i = 0; i < 8; i++)
#pragma unroll
                for (int v = 0; v < 4; v++) s[i][v] = 0.f;
#pragma unroll
            for (int k8 = 0; k8 < 16; k8++) {
                const int kc = k8 * 8 + q;
                uint32_t a[4];
                a[0] = __float_as_uint(Qs[(r0 + g) * AQS + kc]);
                a[1] = __float_as_uint(Qs[(r0 + g + 8) * AQS + kc]);
                a[2] = __float_as_uint(Qs[(r0 + g) * AQS + kc + 4]);
                a[3] = __float_as_uint(Qs[(r0 + g + 8) * AQS + kc + 4]);
#pragma unroll
                for (int nt = 0; nt < 8; nt++) {
                    uint32_t bfr[2];
                    bfr[0] = __float_as_uint(Kcur[(nt * 8 + g) * AKS + kc]);
                    bfr[1] = __float_as_uint(Kcur[(nt * 8 + g) * AKS + kc + 4]);
                    mma16n8k8(s[nt], a, bfr);
                }
            }
            const bool need_mask = (kb * ABK + ABK - 1 > qt * ABQ + r0);
#pragma unroll
            for (int nt = 0; nt < 8; nt++) {
                const int c0 = kb * ABK + nt * 8 + 2 * q;
                s[nt][0] *= scale; s[nt][1] *= scale;
                s[nt][2] *= scale; s[nt][3] *= scale;
                if (need_mask) {
                    if (c0     > rowA)     s[nt][0] = -1e30f;
                    if (c0 + 1 > rowA)     s[nt][1] = -1e30f;
                    if (c0     > rowA + 8) s[nt][2] = -1e30f;
                    if (c0 + 1 > rowA + 8) s[nt][3] = -1e30f;
                }
            }
            float mxA = -INFINITY, mxB = -INFINITY;
#pragma unroll
            for (int nt = 0; nt < 8; nt++) {
                mxA = fmaxf(mxA, fmaxf(s[nt][0], s[nt][1]));
                mxB = fmaxf(mxB, fmaxf(s[nt][2], s[nt][3]));
            }
            mxA = fmaxf(mxA, __shfl_xor_sync(0xffffffffu, mxA, 1));
            mxA = fmaxf(mxA, __shfl_xor_sync(0xffffffffu, mxA, 2));
            mxB = fmaxf(mxB, __shfl_xor_sync(0xffffffffu, mxB, 1));
            mxB = fmaxf(mxB, __shfl_xor_sync(0xffffffffu, mxB, 2));
            const float mnA = fmaxf(mA, mxA), mnB = fmaxf(mB, mxB);
            const float aA = __expf(mA - mnA), aB = __expf(mB - mnB);
            float sumA = 0.f, sumB = 0.f;
#pragma unroll
            for (int nt = 0; nt < 8; nt++) {
                float p0 = __expf(s[nt][0] - mnA), p1 = __expf(s[nt][1] - mnA);
                float p2 = __expf(s[nt][2] - mnB), p3 = __expf(s[nt][3] - mnB);
                sumA += p0 + p1; sumB += p2 + p3;
                float2 pa = {f2tf_f(p0), f2tf_f(p1)};
                float2 pb = {f2tf_f(p2), f2tf_f(p3)};
                *(float2*)(Pw + g * APS + nt * 8 + 2 * q)       = pa;
                *(float2*)(Pw + (g + 8) * APS + nt * 8 + 2 * q) = pb;
            }
            sumA += __shfl_xor_sync(0xffffffffu, sumA, 1);
            sumA += __shfl_xor_sync(0xffffffffu, sumA, 2);
            sumB += __shfl_xor_sync(0xffffffffu, sumB, 1);
            sumB += __shfl_xor_sync(0xffffffffu, sumB, 2);
            lA = lA * aA + sumA;  mA = mnA;
            lB = lB * aB + sumB;  mB = mnB;
#pragma unroll
            for (int nt = 0; nt < 16; nt++) {
                o[nt][0] *= aA; o[nt][1] *= aA;
                o[nt][2] *= aB; o[nt][3] *= aB;
            }
            __syncwarp();
#pragma unroll
            for (int k8 = 0; k8 < 8; k8++) {
                const int kc = k8 * 8 + q;
                uint32_t a[4];
                a[0] = __float_as_uint(Pw[g * APS + kc]);
                a[1] = __float_as_uint(Pw[(g + 8) * APS + kc]);
                a[2] = __float_as_uint(Pw[g * APS + kc + 4]);
                a[3] = __float_as_uint(Pw[(g + 8) * APS + kc + 4]);
#pragma unroll
                for (int nt = 0; nt < 16; nt++) {
                    uint32_t bfr[2];
                    bfr[0] = __float_as_uint(Vs[kc * AVS + nt * 8 + g]);
                    bfr[1] = __float_as_uint(Vs[(kc + 4) * AVS + nt * 8 + g]);
                    mma16n8k8(o[nt], a, bfr);
                }
            }
        }
        __syncthreads();     // everyone done with Vs before refill

        if (kb + 1 < nkb) issueV(kb + 1);
        CP_COMMIT();
    }

    // write tf32-rounded (WO path re-rounds to fp16 anyway)
    const float invA = 1.f / lA, invB = 1.f / lB;
    const size_t baseA = ((size_t)((b * SEQ + rowA) * NH + h)) * HD;
    const size_t baseB = baseA + (size_t)8 * NH * HD;
#pragma unroll
    for (int nt = 0; nt < 16; nt++) {
        float2 va = {f2tf_f(o[nt][0] * invA), f2tf_f(o[nt][1] * invA)};
        float2 vb = {f2tf_f(o[nt][2] * invB), f2tf_f(o[nt][3] * invB)};
        *(float2*)(O + baseA + nt * 8 + 2 * q) = va;
        *(float2*)(O + baseB + nt * 8 + 2 * q) = vb;
    }
}

// ============================================================================
// launch
// ============================================================================
extern "C" void kernel_launch(void* const* d_in, const int* in_sizes, int n_in,
                              void* d_out, int out_size) {
    const float* x    = (const float*)d_in[0];
    const float* fcos = (const float*)d_in[1];
    const float* fsin = (const float*)d_in[2];
    // d_in[3] mask, d_in[4] input_idexes, d_in[5] cache_k, d_in[6] cache_v: unused
    const float* wq = (const float*)d_in[7];
    const float* wk = (const float*)d_in[8];
    const float* wv = (const float*)d_in[9];
    const float* wo = (const float*)d_in[10];

    float* out     = (float*)d_out;                               // [B,S,DIM]
    float* cache_k = (float*)d_out + (size_t)NTOK * DIM;          // [B,S,NH,HD]
    float* cache_v = (float*)d_out + (size_t)2 * NTOK * DIM;      // [B,S,NH,HD]

    float*  qbuf; cudaGetSymbolAddress((void**)&qbuf, g_q);
    float*  abuf; cudaGetSymbolAddress((void**)&abuf, g_att);
    __half* xt;   cudaGetSymbolAddress((void**)&xt,   g_xt);
    __half* wqt;  cudaGetSymbolAddress((void**)&wqt,  g_wqt);
    __half* wkt;  cudaGetSymbolAddress((void**)&wkt,  g_wkt);
    __half* wvt;  cudaGetSymbolAddress((void**)&wvt,  g_wvt);
    __half* wot;  cudaGetSymbolAddress((void**)&wot,  g_wot);

    cudaFuncSetAttribute(gemm_mma,  cudaFuncAttributeMaxDynamicSharedMemorySize, G_SMEM);
    cudaFuncSetAttribute(flash_mma, cudaFuncAttributeMaxDynamicSharedMemorySize, FA_SMEM);

    const int N16 = NTOK * DIM / 16;       // 16-float groups per 64MB buffer
    const int cb = (N16 + 255) / 256;
    cvt_h<<<cb, 256>>>((const float4*)x,  (uint4*)xt,  N16);
    cvt_h<<<cb, 256>>>((const float4*)wq, (uint4*)wqt, N16);
    cvt_h<<<cb, 256>>>((const float4*)wk, (uint4*)wkt, N16);
    cvt_h<<<cb, 256>>>((const float4*)wv, (uint4*)wvt, N16);
    cvt_h<<<cb, 256>>>((const float4*)wo, (uint4*)wot, N16);

    // fused QKV: z=0 -> Q (rope), z=1 -> K (rope), z=2 -> V; outputs tf32-rounded
    dim3 gq(DIM / GTN, NTOK / GTM, 3);     // (32, 16, 3)
    gemm_mma<<<gq, 256, G_SMEM>>>(xt, wqt, wkt, wvt, qbuf, cache_k, cache_v,
                                  fcos, fsin, 1);

    dim3 fg(SEQ / ABQ, NH, BSZ);           // (16, 32, 2)
    flash_mma<<<fg, 256, FA_SMEM>>>(qbuf, cache_k, cache_v, abuf);

    // convert attention output to fp16+perm, then WO gemm
    cvt_h<<<cb, 256>>>((const float4*)abuf, (uint4*)xt, N16);
    dim3 gw(DIM / GTN, NTOK / GTM, 1);     // (32, 16)
    gemm_mma<<<gw, 256, G_SMEM>>>(xt, wot, wot, wot, out, out, out,
                                  nullptr, nullptr, 0);
}

// round 11
// speedup vs baseline: 1.7408x; 1.0912x over previous
#include <cuda_runtime.h>
#include <cuda_fp16.h>
#include <math.h>
#include <stdint.h>

#define DIM   4096
#define NH    32
#define HD    128
#define BSZ   2
#define SEQ   2048
#define NTOK  (BSZ*SEQ)          // 4096 tokens

// ---------------- scratch (allocation-free: __device__ globals) -------------
__device__ float  g_att[(size_t)NTOK * DIM];   // attention out (fp32)
__device__ __half g_xt [(size_t)NTOK * DIM];   // fp16+perm gemm A operand
__device__ __half g_wqt[(size_t)DIM * DIM];    // fp16+perm weights
__device__ __half g_wkt[(size_t)DIM * DIM];
__device__ __half g_wvt[(size_t)DIM * DIM];
__device__ __half g_wot[(size_t)DIM * DIM];
__device__ __half g_qh [(size_t)NTOK * DIM];   // fp16 rotated Q  [b,s,h,d]
__device__ __half g_kh [(size_t)NTOK * DIM];   // fp16 rotated K  [b,s,h,d]
__device__ __half g_vt [(size_t)NTOK * DIM];   // fp16 V transposed [b,h,d,s]

// ============================================================================
// helpers
// ============================================================================
__device__ __forceinline__ uint32_t smem_u32(const void* p) {
    uint32_t a;
    asm("{ .reg .u64 t; cvta.to.shared.u64 t, %1; cvt.u32.u64 %0, t; }"
        : "=r"(a) : "l"(p));
    return a;
}

__device__ __forceinline__ void cp16(uint32_t dst, const void* src) {
    asm volatile("cp.async.cg.shared.global [%0], [%1], 16;" :: "r"(dst), "l"(src));
}
#define CP_COMMIT() asm volatile("cp.async.commit_group;" ::: "memory")
#define CP_WAIT1()  asm volatile("cp.async.wait_group 1;"  ::: "memory")
#define CP_WAIT2()  asm volatile("cp.async.wait_group 2;"  ::: "memory")

__device__ __forceinline__ uint32_t pack_h2(float a, float b) {
    __half2 h = __floats2half2_rn(a, b);
    return *(uint32_t*)&h;
}

// fp16 m16n8k16, fp32 accumulate
__device__ __forceinline__ void mma16n8k16h(float* c, const uint32_t* a, const uint32_t* b) {
    asm volatile(
        "mma.sync.aligned.m16n8k16.row.col.f32.f16.f16.f32 "
        "{%0,%1,%2,%3}, {%4,%5,%6,%7}, {%8,%9}, {%0,%1,%2,%3};"
        : "+f"(c[0]), "+f"(c[1]), "+f"(c[2]), "+f"(c[3])
        : "r"(a[0]), "r"(a[1]), "r"(a[2]), "r"(a[3]), "r"(b[0]), "r"(b[1]));
}

// ============================================================================
// fp32 -> fp16 (rne) + k-group permutation (GEMM operands).
// 16-group [l0..l15] -> halves [l0,l1,l8,l9, l2,l3,l10,l11, ...]:
// fragment halves (2q,2q+1,2q+8,2q+9) = one aligned float2.
// ============================================================================
__global__ __launch_bounds__(256) void cvt_h(const float4* __restrict__ in,
                                             uint4* __restrict__ out, int n16) {
    int i = blockIdx.x * blockDim.x + threadIdx.x;
    if (i < n16) {
        float4 v0 = in[4 * i], v1 = in[4 * i + 1], v2 = in[4 * i + 2], v3 = in[4 * i + 3];
        uint4 o0, o1;
        o0.x = pack_h2(v0.x, v0.y); o0.y = pack_h2(v2.x, v2.y);
        o0.z = pack_h2(v0.z, v0.w); o0.w = pack_h2(v2.z, v2.w);
        o1.x = pack_h2(v1.x, v1.y); o1.y = pack_h2(v3.x, v3.y);
        o1.z = pack_h2(v1.z, v1.w); o1.w = pack_h2(v3.z, v3.w);
        out[2 * i]     = o0;
        out[2 * i + 1] = o1;
    }
}

// ============================================================================
// V transpose: cache_v fp32 [b,s,h,d] -> g_vt fp16 [b,h,d,s]. 32x32 tiles.
// ============================================================================
__global__ __launch_bounds__(256) void vtrans(const float* __restrict__ V,
                                              __half* __restrict__ Vt) {
    __shared__ __half tile[32][33];
    const int tx = threadIdx.x & 31, ty = threadIdx.x >> 5;   // 32 x 8
    const int s0 = blockIdx.x * 32;
    const int d0 = blockIdx.y * 32;
    const int h  = blockIdx.z & (NH - 1);
    const int b  = blockIdx.z >> 5;
#pragma unroll
    for (int j = 0; j < 4; j++) {
        int s = s0 + ty + j * 8;
        tile[ty + j * 8][tx] = __float2half_rn(V[((size_t)((b * SEQ + s) * NH + h)) * HD + d0 + tx]);
    }
    __syncthreads();
#pragma unroll
    for (int j = 0; j < 4; j++) {
        int d = d0 + ty + j * 8;
        Vt[((size_t)((b * NH + h) * HD + d)) * SEQ + s0 + tx] = tile[tx][ty + j * 8];
    }
}

// ============================================================================
// fp16 mma.sync GEMM (NT): C[m,n] = sum_k A[m,k]*B[n,k]
// CTA 256x128, 8 warps (4x2), warp tile 64x64, BK=32 halves, 4-stage pipe.
// mode: 0 = plain fp32 C (WO) | 1 = Q: fp16 H only | 2 = K: fp32 C + fp16 H
//       3 = V: fp32 C (fp16-rounded)
// ============================================================================
#define GTM 256
#define GTN 128
#define GBK 32
#define GTS 48
#define GST 4
#define GNKI (DIM / GBK)                                   // 128
#define G_STAGE ((GTM + GTN) * GTS)                        // halves per stage
#define G_SMEM (GST * G_STAGE * 2)                         // 147456 B

__global__ __launch_bounds__(256, 1) void gemm_mma(
    const __half* __restrict__ A,
    const __half* __restrict__ B0, const __half* __restrict__ B1, const __half* __restrict__ B2,
    float* __restrict__ C0, float* __restrict__ C1, float* __restrict__ C2,
    __half* __restrict__ H0, __half* __restrict__ H1,
    const float* __restrict__ rcs, const float* __restrict__ rsn, int is_qkv) {
    extern __shared__ __half smh[];

    const int z = blockIdx.z;
    const __half* B = (z == 0) ? B0 : ((z == 1) ? B1 : B2);
    float*        C = (z == 0) ? C0 : ((z == 1) ? C1 : C2);
    __half*       H = (z == 0) ? H0 : ((z == 1) ? H1 : nullptr);
    const int  mode = is_qkv ? (z + 1) : 0;
    const bool do_rope = is_qkv && (z < 2);

    const int t    = threadIdx.x;
    const int lane = t & 31;
    const int w    = t >> 5;
    const int wm   = w >> 1;          // 0..3
    const int wn   = w & 1;           // 0..1
    const int g    = lane >> 2;       // 0..7
    const int q    = lane & 3;        // 0..3
    const int bm   = blockIdx.y, bn = blockIdx.x;

    const uint32_t sS = smem_u32(smh);
    const int lr  = t >> 2;           // 0..63
    const int lc8 = (t & 3) * 8;      // half offset 0,8,16,24
    const __half* Agp = A + (size_t)(bm * GTM + lr) * DIM + lc8;
    const __half* Bgp = B + (size_t)(bn * GTN + lr) * DIM + lc8;

    float acc[4][8][4];
#pragma unroll
    for (int i = 0; i < 4; i++)
#pragma unroll
        for (int j = 0; j < 8; j++)
#pragma unroll
            for (int v = 0; v < 4; v++) acc[i][j][v] = 0.f;

    // prologue: stages 0..GST-2
#pragma unroll
    for (int s = 0; s < GST - 1; s++) {
        const int k0 = s * GBK;
        const uint32_t dA = sS + s * (G_STAGE * 2);
        const uint32_t dB = dA + GTM * GTS * 2;
#pragma unroll
        for (int j = 0; j < 4; j++)
            cp16(dA + ((lr + j * 64) * GTS + lc8) * 2, Agp + (size_t)(j * 64) * DIM + k0);
#pragma unroll
        for (int j = 0; j < 2; j++)
            cp16(dB + ((lr + j * 64) * GTS + lc8) * 2, Bgp + (size_t)(j * 64) * DIM + k0);
        CP_COMMIT();
    }

    for (int i = 0; i < GNKI; i++) {
        CP_WAIT2();
        __syncthreads();

        if (i + GST - 1 < GNKI) {
            const int st = (i + GST - 1) & (GST - 1);
            const int k0 = (i + GST - 1) * GBK;
            const uint32_t dA = sS + st * (G_STAGE * 2);
            const uint32_t dB = dA + GTM * GTS * 2;
#pragma unroll
            for (int j = 0; j < 4; j++)
                cp16(dA + ((lr + j * 64) * GTS + lc8) * 2, Agp + (size_t)(j * 64) * DIM + k0);
#pragma unroll
            for (int j = 0; j < 2; j++)
                cp16(dB + ((lr + j * 64) * GTS + lc8) * 2, Bgp + (size_t)(j * 64) * DIM + k0);
        }
        CP_COMMIT();   // empty in tail: keeps group accounting valid

        const __half* Ab = smh + (i & (GST - 1)) * G_STAGE;
        const __half* Bb = Ab + GTM * GTS;
#pragma unroll
        for (int s = 0; s < 2; s++) {
            const int ks = s * 16 + 4 * q;        // permuted slot of (2q,2q+1,2q+8,2q+9)
            uint32_t af[4][4], bf[8][2];
#pragma unroll
            for (int mt = 0; mt < 4; mt++) {
                const int r0 = wm * 64 + mt * 16 + g;
                float2 u0 = *(const float2*)(Ab + r0 * GTS + ks);
                float2 u1 = *(const float2*)(Ab + (r0 + 8) * GTS + ks);
                af[mt][0] = __float_as_uint(u0.x);
                af[mt][1] = __float_as_uint(u1.x);
                af[mt][2] = __float_as_uint(u0.y);
                af[mt][3] = __float_as_uint(u1.y);
            }
#pragma unroll
            for (int nt = 0; nt < 8; nt++) {
                const int c0 = wn * 64 + nt * 8 + g;
                float2 v = *(const float2*)(Bb + c0 * GTS + ks);
                bf[nt][0] = __float_as_uint(v.x);
                bf[nt][1] = __float_as_uint(v.y);
            }
#pragma unroll
            for (int mt = 0; mt < 4; mt++)
#pragma unroll
                for (int nt = 0; nt < 8; nt++)
                    mma16n8k16h(acc[mt][nt], af[mt], bf[nt]);
        }
    }

    // epilogue (fused RoPE for Q/K; per-mode fp32/fp16 stores)
#pragma unroll
    for (int mt = 0; mt < 4; mt++) {
        const size_t row = (size_t)bm * GTM + wm * 64 + mt * 16 + g;
#pragma unroll
        for (int nt = 0; nt < 8; nt++) {
            const int col = bn * GTN + wn * 64 + nt * 8 + q * 2;
            float2 v0 = {acc[mt][nt][0], acc[mt][nt][1]};
            float2 v1 = {acc[mt][nt][2], acc[mt][nt][3]};
            if (do_rope) {
                const int fi = (col & 127) >> 1;
                const int s0 = (int)(row & (SEQ - 1));
                const int s1 = (int)((row + 8) & (SEQ - 1));
                float c0 = rcs[s0 * 64 + fi], sn0 = rsn[s0 * 64 + fi];
                float c1 = rcs[s1 * 64 + fi], sn1 = rsn[s1 * 64 + fi];
                float2 r0 = {v0.x * c0 - v0.y * sn0, v0.x * sn0 + v0.y * c0};
                float2 r1 = {v1.x * c1 - v1.y * sn1, v1.x * sn1 + v1.y * c1};
                v0 = r0; v1 = r1;
            }
            if (mode == 0) {
                *(float2*)(C + row * DIM + col)       = v0;
                *(float2*)(C + (row + 8) * DIM + col) = v1;
            } else {
                __half2 h0 = __floats2half2_rn(v0.x, v0.y);
                __half2 h1 = __floats2half2_rn(v1.x, v1.y);
                if (mode != 3) {   // Q or K: fp16 copy
                    *(__half2*)(H + row * DIM + col)       = h0;
                    *(__half2*)(H + (row + 8) * DIM + col) = h1;
                }
                if (mode != 1) {   // K or V: fp32 cache (fp16-rounded values)
                    float2 f0 = {__low2float(h0), __high2float(h0)};
                    float2 f1 = {__low2float(h1), __high2float(h1)};
                    *(float2*)(C + row * DIM + col)       = f0;
                    *(float2*)(C + (row + 8) * DIM + col) = f1;
                }
            }
        }
    }
}

// ============================================================================
// fp16 flash attention (m16n8k16): BQ=128, BK=64, 8 warps.
// Q/K fp16 [b,s,h,d]; V fp16 transposed [b,h,d,s]. Plain row layouts give
// aligned uint32 fragment loads; strides 136/72 halves conflict-free.
// ============================================================================
#define ABQ 128
#define ABK 64
#define QSH 136
#define VTS 72
#define PSH 72
#define FA_SMEM ((ABQ*QSH + 2*ABK*QSH + HD*VTS + 8*16*PSH) * 2)   // 106496 B

__global__ __launch_bounds__(256, 1) void flash_mma(const __half* __restrict__ Qh,
                                                    const __half* __restrict__ Kh,
                                                    const __half* __restrict__ Vt,
                                                    float* __restrict__ O) {
    extern __shared__ __half smA[];
    __half* Qs = smA;                            // 128 x 136
    __half* Kb = Qs + ABQ * QSH;                 // 2 x (64 x 136)
    __half* Vs = Kb + 2 * ABK * QSH;             // 128(d) x 72
    __half* Ps = Vs + HD * VTS;                  // 8 warps x 16 x 72

    const int t    = threadIdx.x;
    const int w    = t >> 5;
    const int lane = t & 31;
    const int g    = lane >> 2;
    const int q    = lane & 3;
    const int qt   = gridDim.x - 1 - blockIdx.x;   // longest tiles first
    const int h    = blockIdx.y, b = blockIdx.z;
    const float scale = 0.08838834764831845f;      // 1/sqrt(128)

    const uint32_t sQs = smem_u32(Qs);
    const uint32_t sKb = smem_u32(Kb);
    const uint32_t sVs = smem_u32(Vs);
    const int nkb = 2 * (qt + 1);

    // K tile: 64 rows x 128 halves (16 cp16/row)
    auto issueK = [&](int kb, int buf) {
        const uint32_t base = sKb + (uint32_t)buf * (ABK * QSH * 2);
        for (int i = t; i < ABK * 16; i += 256) {
            int row = i >> 4, c = i & 15;
            size_t gk = ((size_t)((b * SEQ + kb * ABK + row) * NH + h)) * HD + c * 8;
            cp16(base + (row * QSH + c * 8) * 2, Kh + gk);
        }
    };
    // V tile: 128 d-rows x 64 halves (8 cp16/row)
    auto issueV = [&](int kb) {
        for (int i = t; i < HD * 8; i += 256) {
            int d = i >> 3, c = i & 7;
            size_t gv = ((size_t)((b * NH + h) * HD + d)) * SEQ + kb * ABK + c * 8;
            cp16(sVs + (d * VTS + c * 8) * 2, Vt + gv);
        }
    };

    // prologue: group0 = K0, group1 = {V0, Q}
    issueK(0, 0); CP_COMMIT();
    issueV(0);
    for (int i = t; i < ABQ * 16; i += 256) {
        int row = i >> 4, c = i & 15;
        size_t gq = ((size_t)((b * SEQ + qt * ABQ + row) * NH + h)) * HD + c * 8;
        cp16(sQs + (row * QSH + c * 8) * 2, Qh + gq);
    }
    CP_COMMIT();

    float o[16][4];
#pragma unroll
    for (int i = 0; i < 16; i++)
#pragma unroll
        for (int v = 0; v < 4; v++) o[i][v] = 0.f;
    float mA = -INFINITY, mB = -INFINITY, lA = 0.f, lB = 0.f;

    __half* Pw = Ps + w * 16 * PSH;
    const int r0   = w * 16;
    const int rowA = qt * ABQ + r0 + g;            // rowB = rowA + 8

    for (int kb = 0; kb < nkb; kb++) {
        if (kb + 1 < nkb) issueK(kb + 1, (kb + 1) & 1);
        CP_COMMIT();
        CP_WAIT1();          // K_kb, V_kb, Q landed
        __syncthreads();

        __half* Kcur = Kb + (kb & 1) * (ABK * QSH);
        const bool full_skip = (kb * ABK > qt * ABQ + r0 + 15);
        if (!full_skip) {
            // ---- S = Q K^T : 8 k16 steps over HD ----
            float s[8][4];
#pragma unroll
            for (int i = 0; i < 8; i++)
#pragma unroll
                for (int v = 0; v < 4; v++) s[i][v] = 0.f;
#pragma unroll
            for (int k16 = 0; k16 < 8; k16++) {
                const int kc = k16 * 16 + 2 * q;
                uint32_t a[4];
                a[0] = *(const uint32_t*)(Qs + (r0 + g) * QSH + kc);
                a[1] = *(const uint32_t*)(Qs + (r0 + g + 8) * QSH + kc);
                a[2] = *(const uint32_t*)(Qs + (r0 + g) * QSH + kc + 8);
                a[3] = *(const uint32_t*)(Qs + (r0 + g + 8) * QSH + kc + 8);
#pragma unroll
                for (int nt = 0; nt < 8; nt++) {
                    uint32_t bfr[2];
                    bfr[0] = *(const uint32_t*)(Kcur + (nt * 8 + g) * QSH + kc);
                    bfr[1] = *(const uint32_t*)(Kcur + (nt * 8 + g) * QSH + kc + 8);
                    mma16n8k16h(s[nt], a, bfr);
                }
            }
            const bool need_mask = (kb * ABK + ABK - 1 > qt * ABQ + r0);
#pragma unroll
            for (int nt = 0; nt < 8; nt++) {
                const int c0 = kb * ABK + nt * 8 + 2 * q;
                s[nt][0] *= scale; s[nt][1] *= scale;
                s[nt][2] *= scale; s[nt][3] *= scale;
                if (need_mask) {
                    if (c0     > rowA)     s[nt][0] = -1e30f;
                    if (c0 + 1 > rowA)     s[nt][1] = -1e30f;
                    if (c0     > rowA + 8) s[nt][2] = -1e30f;
                    if (c0 + 1 > rowA + 8) s[nt][3] = -1e30f;
                }
            }
            float mxA = -INFINITY, mxB = -INFINITY;
#pragma unroll
            for (int nt = 0; nt < 8; nt++) {
                mxA = fmaxf(mxA, fmaxf(s[nt][0], s[nt][1]));
                mxB = fmaxf(mxB, fmaxf(s[nt][2], s[nt][3]));
            }
            mxA = fmaxf(mxA, __shfl_xor_sync(0xffffffffu, mxA, 1));
            mxA = fmaxf(mxA, __shfl_xor_sync(0xffffffffu, mxA, 2));
            mxB = fmaxf(mxB, __shfl_xor_sync(0xffffffffu, mxB, 1));
            mxB = fmaxf(mxB, __shfl_xor_sync(0xffffffffu, mxB, 2));
            const float mnA = fmaxf(mA, mxA), mnB = fmaxf(mB, mxB);
            const float aA = __expf(mA - mnA), aB = __expf(mB - mnB);
            float sumA = 0.f, sumB = 0.f;
#pragma unroll
            for (int nt = 0; nt < 8; nt++) {
                float p0 = __expf(s[nt][0] - mnA), p1 = __expf(s[nt][1] - mnA);
                float p2 = __expf(s[nt][2] - mnB), p3 = __expf(s[nt][3] - mnB);
                sumA += p0 + p1; sumB += p2 + p3;
                *(uint32_t*)(Pw + g * PSH + nt * 8 + 2 * q)       = pack_h2(p0, p1);
                *(uint32_t*)(Pw + (g + 8) * PSH + nt * 8 + 2 * q) = pack_h2(p2, p3);
            }
            sumA += __shfl_xor_sync(0xffffffffu, sumA, 1);
            sumA += __shfl_xor_sync(0xffffffffu, sumA, 2);
            sumB += __shfl_xor_sync(0xffffffffu, sumB, 1);
            sumB += __shfl_xor_sync(0xffffffffu, sumB, 2);
            lA = lA * aA + sumA;  mA = mnA;
            lB = lB * aB + sumB;  mB = mnB;
#pragma unroll
            for (int nt = 0; nt < 16; nt++) {
                o[nt][0] *= aA; o[nt][1] *= aA;
                o[nt][2] *= aB; o[nt][3] *= aB;
            }
            __syncwarp();
            // ---- O += P V : 4 k16 steps over 64 keys, 16 d-tiles ----
#pragma unroll
            for (int k16 = 0; k16 < 4; k16++) {
                const int kc = k16 * 16 + 2 * q;
                uint32_t a[4];
                a[0] = *(const uint32_t*)(Pw + g * PSH + kc);
                a[1] = *(const uint32_t*)(Pw + (g + 8) * PSH + kc);
                a[2] = *(const uint32_t*)(Pw + g * PSH + kc + 8);
                a[3] = *(const uint32_t*)(Pw + (g + 8) * PSH + kc + 8);
#pragma unroll
                for (int nt = 0; nt < 16; nt++) {
                    uint32_t bfr[2];
                    bfr[0] = *(const uint32_t*)(Vs + (nt * 8 + g) * VTS + kc);
                    bfr[1] = *(const uint32_t*)(Vs + (nt * 8 + g) * VTS + kc + 8);
                    mma16n8k16h(o[nt], a, bfr);
                }
            }
        }
        __syncthreads();     // everyone done with Vs before refill

        if (kb + 1 < nkb) issueV(kb + 1);
        CP_COMMIT();
    }

    const float invA = 1.f / lA, invB = 1.f / lB;
    const size_t baseA = ((size_t)((b * SEQ + rowA) * NH + h)) * HD;
    const size_t baseB = baseA + (size_t)8 * NH * HD;
#pragma unroll
    for (int nt = 0; nt < 16; nt++) {
        float2 va = {o[nt][0] * invA, o[nt][1] * invA};
        float2 vb = {o[nt][2] * invB, o[nt][3] * invB};
        *(float2*)(O + baseA + nt * 8 + 2 * q) = va;
        *(float2*)(O + baseB + nt * 8 + 2 * q) = vb;
    }
}

// ============================================================================
// launch
// ============================================================================
extern "C" void kernel_launch(void* const* d_in, const int* in_sizes, int n_in,
                              void* d_out, int out_size) {
    const float* x    = (const float*)d_in[0];
    const float* fcos = (const float*)d_in[1];
    const float* fsin = (const float*)d_in[2];
    // d_in[3] mask, d_in[4] input_idexes, d_in[5] cache_k, d_in[6] cache_v: unused
    const float* wq = (const float*)d_in[7];
    const float* wk = (const float*)d_in[8];
    const float* wv = (const float*)d_in[9];
    const float* wo = (const float*)d_in[10];

    float* out     = (float*)d_out;                               // [B,S,DIM]
    float* cache_k = (float*)d_out + (size_t)NTOK * DIM;          // [B,S,NH,HD]
    float* cache_v = (float*)d_out + (size_t)2 * NTOK * DIM;      // [B,S,NH,HD]

    float*  abuf; cudaGetSymbolAddress((void**)&abuf, g_att);
    __half* xt;   cudaGetSymbolAddress((void**)&xt,   g_xt);
    __half* wqt;  cudaGetSymbolAddress((void**)&wqt,  g_wqt);
    __half* wkt;  cudaGetSymbolAddress((void**)&wkt,  g_wkt);
    __half* wvt;  cudaGetSymbolAddress((void**)&wvt,  g_wvt);
    __half* wot;  cudaGetSymbolAddress((void**)&wot,  g_wot);
    __half* qh;   cudaGetSymbolAddress((void**)&qh,   g_qh);
    __half* kh;   cudaGetSymbolAddress((void**)&kh,   g_kh);
    __half* vt;   cudaGetSymbolAddress((void**)&vt,   g_vt);

    cudaFuncSetAttribute(gemm_mma,  cudaFuncAttributeMaxDynamicSharedMemorySize, G_SMEM);
    cudaFuncSetAttribute(flash_mma, cudaFuncAttributeMaxDynamicSharedMemorySize, FA_SMEM);

    const int N16 = NTOK * DIM / 16;       // 16-float groups per 64MB buffer
    const int cb = (N16 + 255) / 256;
    cvt_h<<<cb, 256>>>((const float4*)x,  (uint4*)xt,  N16);
    cvt_h<<<cb, 256>>>((const float4*)wq, (uint4*)wqt, N16);
    cvt_h<<<cb, 256>>>((const float4*)wk, (uint4*)wkt, N16);
    cvt_h<<<cb, 256>>>((const float4*)wv, (uint4*)wvt, N16);
    cvt_h<<<cb, 256>>>((const float4*)wo, (uint4*)wot, N16);

    // fused QKV: z=0 -> Q (rope, fp16 only), z=1 -> K (rope, fp32+fp16),
    //            z=2 -> V (fp32, fp16-rounded)
    dim3 gq(DIM / GTN, NTOK / GTM, 3);     // (32, 16, 3)
    gemm_mma<<<gq, 256, G_SMEM>>>(xt, wqt, wkt, wvt,
                                  nullptr, cache_k, cache_v,
                                  qh, kh, fcos, fsin, 1);

    // V transpose -> fp16 [b,h,d,s]
    dim3 vg(SEQ / 32, HD / 32, BSZ * NH);  // (64, 4, 64)
    vtrans<<<vg, 256>>>(cache_v, vt);

    dim3 fg(SEQ / ABQ, NH, BSZ);           // (16, 32, 2)
    flash_mma<<<fg, 256, FA_SMEM>>>(qh, kh, vt, abuf);

    // attention out -> fp16+perm, then WO gemm
    cvt_h<<<cb, 256>>>((const float4*)abuf, (uint4*)xt, N16);
    dim3 gw(DIM / GTN, NTOK / GTM, 1);     // (32, 16)
    gemm_mma<<<gw, 256, G_SMEM>>>(xt, wot, wot, wot,
                                  out, out, out,
                                  nullptr, nullptr, nullptr, nullptr, 0);
}

// round 12
// speedup vs baseline: 1.7580x; 1.0099x over previous
#include <cuda_runtime.h>
#include <cuda_fp16.h>
#include <math.h>
#include <stdint.h>

#define DIM   4096
#define NH    32
#define HD    128
#define BSZ   2
#define SEQ   2048
#define NTOK  (BSZ*SEQ)          // 4096 tokens

// ---------------- scratch (allocation-free: __device__ globals) -------------
__device__ __half g_xt [(size_t)NTOK * DIM];   // fp16+perm gemm A operand (x, then attn-out)
__device__ __half g_wqt[(size_t)DIM * DIM];    // fp16+perm weights
__device__ __half g_wkt[(size_t)DIM * DIM];
__device__ __half g_wvt[(size_t)DIM * DIM];
__device__ __half g_wot[(size_t)DIM * DIM];
__device__ __half g_qh [(size_t)NTOK * DIM];   // fp16 rotated Q, d-perm  [b,s,h,d]
__device__ __half g_kh [(size_t)NTOK * DIM];   // fp16 rotated K, d-perm  [b,s,h,d]
__device__ __half g_vt [(size_t)NTOK * DIM];   // fp16 V transposed, s-perm [b,h,d,s]

// ============================================================================
// helpers
// ============================================================================
__device__ __forceinline__ uint32_t smem_u32(const void* p) {
    uint32_t a;
    asm("{ .reg .u64 t; cvta.to.shared.u64 t, %1; cvt.u32.u64 %0, t; }"
        : "=r"(a) : "l"(p));
    return a;
}

__device__ __forceinline__ void cp16(uint32_t dst, const void* src) {
    asm volatile("cp.async.cg.shared.global [%0], [%1], 16;" :: "r"(dst), "l"(src));
}
#define CP_COMMIT() asm volatile("cp.async.commit_group;" ::: "memory")
#define CP_WAIT1()  asm volatile("cp.async.wait_group 1;"  ::: "memory")
#define CP_WAIT2()  asm volatile("cp.async.wait_group 2;"  ::: "memory")

__device__ __forceinline__ uint32_t pack_h2(float a, float b) {
    __half2 h = __floats2half2_rn(a, b);
    return *(uint32_t*)&h;
}

// fp16 m16n8k16, fp32 accumulate
__device__ __forceinline__ void mma16n8k16h(float* c, const uint32_t* a, const uint32_t* b) {
    asm volatile(
        "mma.sync.aligned.m16n8k16.row.col.f32.f16.f16.f32 "
        "{%0,%1,%2,%3}, {%4,%5,%6,%7}, {%8,%9}, {%0,%1,%2,%3};"
        : "+f"(c[0]), "+f"(c[1]), "+f"(c[2]), "+f"(c[3])
        : "r"(a[0]), "r"(a[1]), "r"(a[2]), "r"(a[3]), "r"(b[0]), "r"(b[1]));
}

// ============================================================================
// fp32 -> fp16 (rne) + k-group permutation (GEMM operands).
// 16-group [l0..l15] -> halves [l0,l1,l8,l9, l2,l3,l10,l11, ...]:
// fragment halves (2q,2q+1,2q+8,2q+9) = one aligned float2.
// ============================================================================
__global__ __launch_bounds__(256) void cvt_h(const float4* __restrict__ in,
                                             uint4* __restrict__ out, int n16) {
    int i = blockIdx.x * blockDim.x + threadIdx.x;
    if (i < n16) {
        float4 v0 = in[4 * i], v1 = in[4 * i + 1], v2 = in[4 * i + 2], v3 = in[4 * i + 3];
        uint4 o0, o1;
        o0.x = pack_h2(v0.x, v0.y); o0.y = pack_h2(v2.x, v2.y);
        o0.z = pack_h2(v0.z, v0.w); o0.w = pack_h2(v2.z, v2.w);
        o1.x = pack_h2(v1.x, v1.y); o1.y = pack_h2(v3.x, v3.y);
        o1.z = pack_h2(v1.z, v1.w); o1.w = pack_h2(v3.z, v3.w);
        out[2 * i]     = o0;
        out[2 * i + 1] = o1;
    }
}

// perm of index l within a 16-group: pair p=l/2 -> uint32 slot 2*(p&3)+(p>>2)
__device__ __forceinline__ int perm16(int l) {
    int p = l >> 1;
    return 4 * (p & 3) + 2 * (p >> 2) + (l & 1);
}

// ============================================================================
// V transpose: cache_v fp32 [b,s,h,d] -> g_vt fp16 [b,h,d,s] with s-perm.
// ============================================================================
__global__ __launch_bounds__(256) void vtrans(const float* __restrict__ V,
                                              __half* __restrict__ Vt) {
    __shared__ __half tile[32][33];
    const int tx = threadIdx.x & 31, ty = threadIdx.x >> 5;   // 32 x 8
    const int s0 = blockIdx.x * 32;
    const int d0 = blockIdx.y * 32;
    const int h  = blockIdx.z & (NH - 1);
    const int b  = blockIdx.z >> 5;
#pragma unroll
    for (int j = 0; j < 4; j++) {
        int s = s0 + ty + j * 8;
        tile[ty + j * 8][tx] = __float2half_rn(V[((size_t)((b * SEQ + s) * NH + h)) * HD + d0 + tx]);
    }
    __syncthreads();
    const int sp = s0 + (tx & 16) + perm16(tx & 15);          // permuted s position
#pragma unroll
    for (int j = 0; j < 4; j++) {
        int d = d0 + ty + j * 8;
        Vt[((size_t)((b * NH + h) * HD + d)) * SEQ + sp] = tile[tx][ty + j * 8];
    }
}

// ============================================================================
// fp16 mma.sync GEMM (NT): C[m,n] = sum_k A[m,k]*B[n,k]
// CTA 256x128, 8 warps (4x2), warp tile 64x64, BK=32 halves, 4-stage pipe.
// mode: 0 = plain fp32 C (WO) | 1 = Q: perm-fp16 H only | 2 = K: fp32 C +
//       perm-fp16 H | 3 = V: fp32 C (fp16-rounded)
// ============================================================================
#define GTM 256
#define GTN 128
#define GBK 32
#define GTS 48
#define GST 4
#define GNKI (DIM / GBK)                                   // 128
#define G_STAGE ((GTM + GTN) * GTS)                        // halves per stage
#define G_SMEM (GST * G_STAGE * 2)                         // 147456 B

__global__ __launch_bounds__(256, 1) void gemm_mma(
    const __half* __restrict__ A,
    const __half* __restrict__ B0, const __half* __restrict__ B1, const __half* __restrict__ B2,
    float* __restrict__ C0, float* __restrict__ C1, float* __restrict__ C2,
    __half* __restrict__ H0, __half* __restrict__ H1,
    const float* __restrict__ rcs, const float* __restrict__ rsn, int is_qkv) {
    extern __shared__ __half smh[];

    const int z = blockIdx.z;
    const __half* B = (z == 0) ? B0 : ((z == 1) ? B1 : B2);
    float*        C = (z == 0) ? C0 : ((z == 1) ? C1 : C2);
    __half*       H = (z == 0) ? H0 : ((z == 1) ? H1 : nullptr);
    const int  mode = is_qkv ? (z + 1) : 0;
    const bool do_rope = is_qkv && (z < 2);

    const int t    = threadIdx.x;
    const int lane = t & 31;
    const int w    = t >> 5;
    const int wm   = w >> 1;          // 0..3
    const int wn   = w & 1;           // 0..1
    const int g    = lane >> 2;       // 0..7
    const int q    = lane & 3;        // 0..3
    const int bm   = blockIdx.y, bn = blockIdx.x;

    const uint32_t sS = smem_u32(smh);
    const int lr  = t >> 2;           // 0..63
    const int lc8 = (t & 3) * 8;      // half offset 0,8,16,24
    const __half* Agp = A + (size_t)(bm * GTM + lr) * DIM + lc8;
    const __half* Bgp = B + (size_t)(bn * GTN + lr) * DIM + lc8;

    float acc[4][8][4];
#pragma unroll
    for (int i = 0; i < 4; i++)
#pragma unroll
        for (int j = 0; j < 8; j++)
#pragma unroll
            for (int v = 0; v < 4; v++) acc[i][j][v] = 0.f;

    // prologue: stages 0..GST-2
#pragma unroll
    for (int s = 0; s < GST - 1; s++) {
        const int k0 = s * GBK;
        const uint32_t dA = sS + s * (G_STAGE * 2);
        const uint32_t dB = dA + GTM * GTS * 2;
#pragma unroll
        for (int j = 0; j < 4; j++)
            cp16(dA + ((lr + j * 64) * GTS + lc8) * 2, Agp + (size_t)(j * 64) * DIM + k0);
#pragma unroll
        for (int j = 0; j < 2; j++)
            cp16(dB + ((lr + j * 64) * GTS + lc8) * 2, Bgp + (size_t)(j * 64) * DIM + k0);
        CP_COMMIT();
    }

    for (int i = 0; i < GNKI; i++) {
        CP_WAIT2();
        __syncthreads();

        if (i + GST - 1 < GNKI) {
            const int st = (i + GST - 1) & (GST - 1);
            const int k0 = (i + GST - 1) * GBK;
            const uint32_t dA = sS + st * (G_STAGE * 2);
            const uint32_t dB = dA + GTM * GTS * 2;
#pragma unroll
            for (int j = 0; j < 4; j++)
                cp16(dA + ((lr + j * 64) * GTS + lc8) * 2, Agp + (size_t)(j * 64) * DIM + k0);
#pragma unroll
            for (int j = 0; j < 2; j++)
                cp16(dB + ((lr + j * 64) * GTS + lc8) * 2, Bgp + (size_t)(j * 64) * DIM + k0);
        }
        CP_COMMIT();   // empty in tail: keeps group accounting valid

        const __half* Ab = smh + (i & (GST - 1)) * G_STAGE;
        const __half* Bb = Ab + GTM * GTS;
#pragma unroll
        for (int s = 0; s < 2; s++) {
            const int ks = s * 16 + 4 * q;        // permuted slot of (2q,2q+1,2q+8,2q+9)
            uint32_t af[4][4], bf[8][2];
#pragma unroll
            for (int mt = 0; mt < 4; mt++) {
                const int r0 = wm * 64 + mt * 16 + g;
                float2 u0 = *(const float2*)(Ab + r0 * GTS + ks);
                float2 u1 = *(const float2*)(Ab + (r0 + 8) * GTS + ks);
                af[mt][0] = __float_as_uint(u0.x);
                af[mt][1] = __float_as_uint(u1.x);
                af[mt][2] = __float_as_uint(u0.y);
                af[mt][3] = __float_as_uint(u1.y);
            }
#pragma unroll
            for (int nt = 0; nt < 8; nt++) {
                const int c0 = wn * 64 + nt * 8 + g;
                float2 v = *(const float2*)(Bb + c0 * GTS + ks);
                bf[nt][0] = __float_as_uint(v.x);
                bf[nt][1] = __float_as_uint(v.y);
            }
#pragma unroll
            for (int mt = 0; mt < 4; mt++)
#pragma unroll
                for (int nt = 0; nt < 8; nt++)
                    mma16n8k16h(acc[mt][nt], af[mt], bf[nt]);
        }
    }

    // epilogue (fused RoPE for Q/K; per-mode fp32/perm-fp16 stores)
#pragma unroll
    for (int mt = 0; mt < 4; mt++) {
        const size_t row = (size_t)bm * GTM + wm * 64 + mt * 16 + g;
#pragma unroll
        for (int nt = 0; nt < 8; nt++) {
            const int col = bn * GTN + wn * 64 + nt * 8 + q * 2;
            float2 v0 = {acc[mt][nt][0], acc[mt][nt][1]};
            float2 v1 = {acc[mt][nt][2], acc[mt][nt][3]};
            if (do_rope) {
                const int fi = (col & 127) >> 1;
                const int s0 = (int)(row & (SEQ - 1));
                const int s1 = (int)((row + 8) & (SEQ - 1));
                float c0 = rcs[s0 * 64 + fi], sn0 = rsn[s0 * 64 + fi];
                float c1 = rcs[s1 * 64 + fi], sn1 = rsn[s1 * 64 + fi];
                float2 r0 = {v0.x * c0 - v0.y * sn0, v0.x * sn0 + v0.y * c0};
                float2 r1 = {v1.x * c1 - v1.y * sn1, v1.x * sn1 + v1.y * c1};
                v0 = r0; v1 = r1;
            }
            if (mode == 0) {
                *(float2*)(C + row * DIM + col)       = v0;
                *(float2*)(C + (row + 8) * DIM + col) = v1;
            } else {
                __half2 h0 = __floats2half2_rn(v0.x, v0.y);
                __half2 h1 = __floats2half2_rn(v1.x, v1.y);
                if (mode != 3) {   // Q or K: perm-fp16 copy
                    const size_t pcol = (size_t)(col & ~15) + 4 * q + 2 * (nt & 1);
                    *(__half2*)(H + row * DIM + pcol)       = h0;
                    *(__half2*)(H + (row + 8) * DIM + pcol) = h1;
                }
                if (mode != 1) {   // K or V: fp32 cache (fp16-rounded values)
                    float2 f0 = {__low2float(h0), __high2float(h0)};
                    float2 f1 = {__low2float(h1), __high2float(h1)};
                    *(float2*)(C + row * DIM + col)       = f0;
                    *(float2*)(C + (row + 8) * DIM + col) = f1;
                }
            }
        }
    }
}

// ============================================================================
// fp16 flash attention (m16n8k16), all-perm layout: every fragment load is
// one LDS.64. BQ=128, BK=64, 8 warps. Strides 144/80 halves: bank index
// 8g+2q distinct per 16-lane phase. Output written perm-fp16 straight into
// the WO GEMM's A buffer (no fp32 abuf, no cvt pass).
// ============================================================================
#define ABQ 128
#define ABK 64
#define QSH 144
#define VTS 80
#define PSH 80
#define FA_SMEM ((ABQ*QSH + 2*ABK*QSH + HD*VTS + 8*16*PSH) * 2)   // 114688 B

__global__ __launch_bounds__(256, 1) void flash_mma(const __half* __restrict__ Qh,
                                                    const __half* __restrict__ Kh,
                                                    const __half* __restrict__ Vt,
                                                    __half* __restrict__ Xt) {
    extern __shared__ __half smA[];
    __half* Qs = smA;                            // 128 x 144
    __half* Kb = Qs + ABQ * QSH;                 // 2 x (64 x 144)
    __half* Vs = Kb + 2 * ABK * QSH;             // 128(d) x 80
    __half* Ps = Vs + HD * VTS;                  // 8 warps x 16 x 80

    const int t    = threadIdx.x;
    const int w    = t >> 5;
    const int lane = t & 31;
    const int g    = lane >> 2;
    const int q    = lane & 3;
    const int qt   = gridDim.x - 1 - blockIdx.x;   // longest tiles first
    const int h    = blockIdx.y, b = blockIdx.z;
    const float scale = 0.08838834764831845f;      // 1/sqrt(128)

    const uint32_t sQs = smem_u32(Qs);
    const uint32_t sKb = smem_u32(Kb);
    const uint32_t sVs = smem_u32(Vs);
    const int nkb = 2 * (qt + 1);

    auto issueK = [&](int kb, int buf) {
        const uint32_t base = sKb + (uint32_t)buf * (ABK * QSH * 2);
        for (int i = t; i < ABK * 16; i += 256) {
            int row = i >> 4, c = i & 15;
            size_t gk = ((size_t)((b * SEQ + kb * ABK + row) * NH + h)) * HD + c * 8;
            cp16(base + (row * QSH + c * 8) * 2, Kh + gk);
        }
    };
    auto issueV = [&](int kb) {
        for (int i = t; i < HD * 8; i += 256) {
            int d = i >> 3, c = i & 7;
            size_t gv = ((size_t)((b * NH + h) * HD + d)) * SEQ + kb * ABK + c * 8;
            cp16(sVs + (d * VTS + c * 8) * 2, Vt + gv);
        }
    };

    // prologue: group0 = K0, group1 = {V0, Q}
    issueK(0, 0); CP_COMMIT();
    issueV(0);
    for (int i = t; i < ABQ * 16; i += 256) {
        int row = i >> 4, c = i & 15;
        size_t gq = ((size_t)((b * SEQ + qt * ABQ + row) * NH + h)) * HD + c * 8;
        cp16(sQs + (row * QSH + c * 8) * 2, Qh + gq);
    }
    CP_COMMIT();

    float o[16][4];
#pragma unroll
    for (int i = 0; i < 16; i++)
#pragma unroll
        for (int v = 0; v < 4; v++) o[i][v] = 0.f;
    float mA = -INFINITY, mB = -INFINITY, lA = 0.f, lB = 0.f;

    __half* Pw = Ps + w * 16 * PSH;
    const int r0   = w * 16;
    const int rowA = qt * ABQ + r0 + g;            // rowB = rowA + 8

    for (int kb = 0; kb < nkb; kb++) {
        if (kb + 1 < nkb) issueK(kb + 1, (kb + 1) & 1);
        CP_COMMIT();
        CP_WAIT1();          // K_kb, V_kb, Q landed
        __syncthreads();

        __half* Kcur = Kb + (kb & 1) * (ABK * QSH);
        const bool full_skip = (kb * ABK > qt * ABQ + r0 + 15);
        if (!full_skip) {
            // ---- S = Q K^T : 8 k16 steps, all LDS.64 ----
            float s[8][4];
#pragma unroll
            for (int i = 0; i < 8; i++)
#pragma unroll
                for (int v = 0; v < 4; v++) s[i][v] = 0.f;
#pragma unroll
            for (int k16 = 0; k16 < 8; k16++) {
                const int ks = k16 * 16 + 4 * q;
                uint32_t a[4];
                float2 u0 = *(const float2*)(Qs + (r0 + g) * QSH + ks);
                float2 u1 = *(const float2*)(Qs + (r0 + g + 8) * QSH + ks);
                a[0] = __float_as_uint(u0.x);
                a[1] = __float_as_uint(u1.x);
                a[2] = __float_as_uint(u0.y);
                a[3] = __float_as_uint(u1.y);
#pragma unroll
                for (int nt = 0; nt < 8; nt++) {
                    float2 v = *(const float2*)(Kcur + (nt * 8 + g) * QSH + ks);
                    uint32_t bfr[2];
                    bfr[0] = __float_as_uint(v.x);
                    bfr[1] = __float_as_uint(v.y);
                    mma16n8k16h(s[nt], a, bfr);
                }
            }
            const bool need_mask = (kb * ABK + ABK - 1 > qt * ABQ + r0);
#pragma unroll
            for (int nt = 0; nt < 8; nt++) {
                const int c0 = kb * ABK + nt * 8 + 2 * q;
                s[nt][0] *= scale; s[nt][1] *= scale;
                s[nt][2] *= scale; s[nt][3] *= scale;
                if (need_mask) {
                    if (c0     > rowA)     s[nt][0] = -1e30f;
                    if (c0 + 1 > rowA)     s[nt][1] = -1e30f;
                    if (c0     > rowA + 8) s[nt][2] = -1e30f;
                    if (c0 + 1 > rowA + 8) s[nt][3] = -1e30f;
                }
            }
            float mxA = -INFINITY, mxB = -INFINITY;
#pragma unroll
            for (int nt = 0; nt < 8; nt++) {
                mxA = fmaxf(mxA, fmaxf(s[nt][0], s[nt][1]));
                mxB = fmaxf(mxB, fmaxf(s[nt][2], s[nt][3]));
            }
            mxA = fmaxf(mxA, __shfl_xor_sync(0xffffffffu, mxA, 1));
            mxA = fmaxf(mxA, __shfl_xor_sync(0xffffffffu, mxA, 2));
            mxB = fmaxf(mxB, __shfl_xor_sync(0xffffffffu, mxB, 1));
            mxB = fmaxf(mxB, __shfl_xor_sync(0xffffffffu, mxB, 2));
            const float mnA = fmaxf(mA, mxA), mnB = fmaxf(mB, mxB);
            const float aA = __expf(mA - mnA), aB = __expf(mB - mnB);
            float sumA = 0.f, sumB = 0.f;
#pragma unroll
            for (int nt = 0; nt < 8; nt++) {
                float p0 = __expf(s[nt][0] - mnA), p1 = __expf(s[nt][1] - mnA);
                float p2 = __expf(s[nt][2] - mnB), p3 = __expf(s[nt][3] - mnB);
                sumA += p0 + p1; sumB += p2 + p3;
                const int po = (nt >> 1) * 16 + 4 * q + 2 * (nt & 1);   // perm slot
                *(uint32_t*)(Pw + g * PSH + po)       = pack_h2(p0, p1);
                *(uint32_t*)(Pw + (g + 8) * PSH + po) = pack_h2(p2, p3);
            }
            sumA += __shfl_xor_sync(0xffffffffu, sumA, 1);
            sumA += __shfl_xor_sync(0xffffffffu, sumA, 2);
            sumB += __shfl_xor_sync(0xffffffffu, sumB, 1);
            sumB += __shfl_xor_sync(0xffffffffu, sumB, 2);
            lA = lA * aA + sumA;  mA = mnA;
            lB = lB * aB + sumB;  mB = mnB;
#pragma unroll
            for (int nt = 0; nt < 16; nt++) {
                o[nt][0] *= aA; o[nt][1] *= aA;
                o[nt][2] *= aB; o[nt][3] *= aB;
            }
            __syncwarp();
            // ---- O += P V : 4 k16 steps, all LDS.64 ----
#pragma unroll
            for (int k16 = 0; k16 < 4; k16++) {
                const int ks = k16 * 16 + 4 * q;
                uint32_t a[4];
                float2 u0 = *(const float2*)(Pw + g * PSH + ks);
                float2 u1 = *(const float2*)(Pw + (g + 8) * PSH + ks);
                a[0] = __float_as_uint(u0.x);
                a[1] = __float_as_uint(u1.x);
                a[2] = __float_as_uint(u0.y);
                a[3] = __float_as_uint(u1.y);
#pragma unroll
                for (int nt = 0; nt < 16; nt++) {
                    float2 v = *(const float2*)(Vs + (nt * 8 + g) * VTS + ks);
                    uint32_t bfr[2];
                    bfr[0] = __float_as_uint(v.x);
                    bfr[1] = __float_as_uint(v.y);
                    mma16n8k16h(o[nt], a, bfr);
                }
            }
        }
        __syncthreads();     // everyone done with Vs before refill

        if (kb + 1 < nkb) issueV(kb + 1);
        CP_COMMIT();
    }

    // write perm-fp16 directly into the WO GEMM's A operand
    const float invA = 1.f / lA, invB = 1.f / lB;
    const size_t baseA = ((size_t)(b * SEQ + rowA)) * DIM + h * HD;
    const size_t baseB = baseA + (size_t)8 * DIM;
#pragma unroll
    for (int ng = 0; ng < 8; ng++) {
        uint2 va = {pack_h2(o[2*ng][0] * invA, o[2*ng][1] * invA),
                    pack_h2(o[2*ng+1][0] * invA, o[2*ng+1][1] * invA)};
        uint2 vb = {pack_h2(o[2*ng][2] * invB, o[2*ng][3] * invB),
                    pack_h2(o[2*ng+1][2] * invB, o[2*ng+1][3] * invB)};
        *(uint2*)(Xt + baseA + ng * 16 + 4 * q) = va;
        *(uint2*)(Xt + baseB + ng * 16 + 4 * q) = vb;
    }
}

// ============================================================================
// launch
// ============================================================================
extern "C" void kernel_launch(void* const* d_in, const int* in_sizes, int n_in,
                              void* d_out, int out_size) {
    const float* x    = (const float*)d_in[0];
    const float* fcos = (const float*)d_in[1];
    const float* fsin = (const float*)d_in[2];
    // d_in[3] mask, d_in[4] input_idexes, d_in[5] cache_k, d_in[6] cache_v: unused
    const float* wq = (const float*)d_in[7];
    const float* wk = (const float*)d_in[8];
    const float* wv = (const float*)d_in[9];
    const float* wo = (const float*)d_in[10];

    float* out     = (float*)d_out;                               // [B,S,DIM]
    float* cache_k = (float*)d_out + (size_t)NTOK * DIM;          // [B,S,NH,HD]
    float* cache_v = (float*)d_out + (size_t)2 * NTOK * DIM;      // [B,S,NH,HD]

    __half* xt;   cudaGetSymbolAddress((void**)&xt,   g_xt);
    __half* wqt;  cudaGetSymbolAddress((void**)&wqt,  g_wqt);
    __half* wkt;  cudaGetSymbolAddress((void**)&wkt,  g_wkt);
    __half* wvt;  cudaGetSymbolAddress((void**)&wvt,  g_wvt);
    __half* wot;  cudaGetSymbolAddress((void**)&wot,  g_wot);
    __half* qh;   cudaGetSymbolAddress((void**)&qh,   g_qh);
    __half* kh;   cudaGetSymbolAddress((void**)&kh,   g_kh);
    __half* vt;   cudaGetSymbolAddress((void**)&vt,   g_vt);

    cudaFuncSetAttribute(gemm_mma,  cudaFuncAttributeMaxDynamicSharedMemorySize, G_SMEM);
    cudaFuncSetAttribute(flash_mma, cudaFuncAttributeMaxDynamicSharedMemorySize, FA_SMEM);

    const int N16 = NTOK * DIM / 16;       // 16-float groups per 64MB buffer
    const int cb = (N16 + 255) / 256;
    cvt_h<<<cb, 256>>>((const float4*)x,  (uint4*)xt,  N16);
    cvt_h<<<cb, 256>>>((const float4*)wq, (uint4*)wqt, N16);
    cvt_h<<<cb, 256>>>((const float4*)wk, (uint4*)wkt, N16);
    cvt_h<<<cb, 256>>>((const float4*)wv, (uint4*)wvt, N16);
    cvt_h<<<cb, 256>>>((const float4*)wo, (uint4*)wot, N16);

    // fused QKV: z=0 -> Q (rope, perm-fp16 only), z=1 -> K (rope, fp32+perm-fp16),
    //            z=2 -> V (fp32, fp16-rounded)
    dim3 gq(DIM / GTN, NTOK / GTM, 3);     // (32, 16, 3)
    gemm_mma<<<gq, 256, G_SMEM>>>(xt, wqt, wkt, wvt,
                                  nullptr, cache_k, cache_v,
                                  qh, kh, fcos, fsin, 1);

    // V transpose -> perm-fp16 [b,h,d,s]
    dim3 vg(SEQ / 32, HD / 32, BSZ * NH);  // (64, 4, 64)
    vtrans<<<vg, 256>>>(cache_v, vt);

    // flash writes perm-fp16 attention output straight into xt
    dim3 fg(SEQ / ABQ, NH, BSZ);           // (16, 32, 2)
    flash_mma<<<fg, 256, FA_SMEM>>>(qh, kh, vt, xt);

    dim3 gw(DIM / GTN, NTOK / GTM, 1);     // (32, 16)
    gemm_mma<<<gw, 256, G_SMEM>>>(xt, wot, wot, wot,
                                  out, out, out,
                                  nullptr, nullptr, nullptr, nullptr, 0);
}